// round 13
// baseline (speedup 1.0000x reference)
#include <cuda_runtime.h>
#include <cuda_fp16.h>
#include <math.h>
#include <stdint.h>

#define D 128
#define NMAX 100000
#define EMAX 800000
#define PMAX 100000
#define WELEM 16384

// ---------------- scratch (device globals; no allocation allowed) ----------
__device__ __align__(16) __half g_hA[NMAX * D];
__device__ __align__(16) __half g_hB[NMAX * D];   // holds half(x) for layer 0
__device__ __align__(16) __half g_z2[2 * PMAX * D];
__device__ __align__(16) __half g_wc[8 * WELEM];  // weights: half, transposed [n][k]
__device__ int   g_deg[NMAX];
__device__ int   g_rowstart[NMAX];
__device__ int   g_cursor[NMAX];
__device__ int   g_csrsrc[EMAX];
__device__ int   g_bsum[256];
__device__ int   g_boff[256];

// ---------------- operand pre-conversion -----------------------------------
struct WPtrs { const float* p[8]; };

__global__ void convw_k(WPtrs w, __half* out) {
    int m = blockIdx.y;
    int i = blockIdx.x * 256 + threadIdx.x;
    if (i < WELEM) {
        int k = i >> 7, n = i & 127;
        out[m * WELEM + n * 128 + k] = __float2half_rn(w.p[m][i]);
    }
}

__global__ void convx_k(const float* __restrict__ in, __half* __restrict__ out, int n) {
    int i = blockIdx.x * 256 + threadIdx.x;
    if (i < n) out[i] = __float2half_rn(in[i]);
}

// ---------------- CSR build ------------------------------------------------
__global__ void zero_k(int n) {
    int i = blockIdx.x * blockDim.x + threadIdx.x;
    if (i < n) { g_deg[i] = 0; g_cursor[i] = 0; }
}

__global__ void hist_k(const int* __restrict__ dst, int E) {
    int e = blockIdx.x * blockDim.x + threadIdx.x;
    if (e < E) atomicAdd(&g_deg[dst[e]], 1);
}

__global__ void scan1_k(int n) {
    __shared__ int s[512];
    int tid = threadIdx.x;
    int i = blockIdx.x * 512 + tid;
    int v = (i < n) ? g_deg[i] : 0;
    s[tid] = v;
    __syncthreads();
    for (int off = 1; off < 512; off <<= 1) {
        int t = (tid >= off) ? s[tid - off] : 0;
        __syncthreads();
        s[tid] += t;
        __syncthreads();
    }
    if (i < n) g_rowstart[i] = s[tid] - v;
    if (tid == 511) g_bsum[blockIdx.x] = s[511];
}

__global__ void scan2_k(int nb) {
    __shared__ int s[256];
    int tid = threadIdx.x;
    int v = (tid < nb) ? g_bsum[tid] : 0;
    s[tid] = v;
    __syncthreads();
    for (int off = 1; off < 256; off <<= 1) {
        int t = (tid >= off) ? s[tid - off] : 0;
        __syncthreads();
        s[tid] += t;
        __syncthreads();
    }
    g_boff[tid] = s[tid] - v;
}

__global__ void scan3_k(int n) {
    int i = blockIdx.x * blockDim.x + threadIdx.x;
    if (i < n) g_rowstart[i] += g_boff[i >> 9];
}

__global__ void scatter_k(const int* __restrict__ src, const int* __restrict__ dst, int E) {
    int e = blockIdx.x * blockDim.x + threadIdx.x;
    if (e >= E) return;
    int d = dst[e];
    int p = atomicAdd(&g_cursor[d], 1);
    g_csrsrc[g_rowstart[d] + p] = src[e];
}

// ---------------- fp16 tensor-core GEMM with fused operand builders --------
// 128x128 tile, 8 warps 4x2 (warp 32x64), BK=64, cp.async 2-buffer, ldmatrix.
// mode 0: C = act(A@W + bias)                  (A via cp.async)
// mode 1: C = act(A@W + agg(A)@W2 + bias)      (agg built in smem per CTA)
// mode 2: C = act((A[s]*A[d])@W + bias)        (pair-product A in loader)
// probOut != null: fused @Wp2+bp2 -> softmax[:,1] epilogue.
#define BK 64
#define SAB_S 36
#define TILE_W (128 * SAB_S)                 // 4608 words
#define AGG_OFF (4 * TILE_W)                 // word offset of agg/pair region
#define GEMM_SMEM (6 * TILE_W * 4)           // 110592 bytes

__device__ __forceinline__ void cp16(uint32_t dst, const void* src, bool pred) {
    int sz = pred ? 16 : 0;
    asm volatile("cp.async.cg.shared.global [%0], [%1], 16, %2;\n"
                 :: "r"(dst), "l"(src), "r"(sz));
}

__device__ __forceinline__ void ldsm4(uint32_t& r0, uint32_t& r1, uint32_t& r2,
                                      uint32_t& r3, uint32_t addr) {
    asm volatile("ldmatrix.sync.aligned.m8n8.x4.shared.b16 {%0,%1,%2,%3}, [%4];"
                 : "=r"(r0), "=r"(r1), "=r"(r2), "=r"(r3) : "r"(addr));
}

__global__ void __launch_bounds__(256) gemm_tc_k(
    const __half* __restrict__ A,
    const __half* __restrict__ W, const __half* __restrict__ W2,
    const float* __restrict__ bias, __half* __restrict__ C,
    int M, int doRelu, int mode,
    const int* __restrict__ ps, const int* __restrict__ pd,
    const int* __restrict__ ns, const int* __restrict__ nd, int Pp,
    float* __restrict__ probOut,
    const float* __restrict__ Wp2, const float* __restrict__ bp2)
{
    extern __shared__ uint32_t smem[];
    int tid = threadIdx.x;
    int lane = tid & 31;
    int w = tid >> 5;
    int wr = w >> 1, wc = w & 1;
    int blockRow = blockIdx.x * 128;
    int lq = lane >> 2;
    int lr = lane & 3;

    uint32_t sbase = (uint32_t)__cvta_generic_to_shared(smem);
    int* sPair = (int*)(smem + AGG_OFF);

    int T = (mode == 1) ? 4 : 2;

    int aRowOff0 = (wr * 32 + (lane & 7) + ((lane >> 3) & 1) * 8) * SAB_S
                 + (lane >> 4) * 4;
    int bRowOff0 = (wc * 64 + ((lane >> 4) & 1) * 8 + (lane & 7)) * SAB_S
                 + ((lane >> 3) & 1) * 4;

    float cAcc[2][8][4];
#pragma unroll
    for (int mt = 0; mt < 2; mt++)
#pragma unroll
        for (int nt = 0; nt < 8; nt++)
#pragma unroll
            for (int i = 0; i < 4; i++) cAcc[mt][nt][i] = 0.f;

    if (mode == 2) {
        if (tid < 128) {
            int row = blockRow + tid;
            int s = 0, dd = 0;
            if (row < M) {
                if (row < Pp) { s = ps[row]; dd = pd[row]; }
                else          { s = ns[row - Pp]; dd = nd[row - Pp]; }
            }
            sPair[tid] = s;
            sPair[128 + tid] = dd;
        }
        __syncthreads();
    }

    auto loadTile = [&](int t, int buf) {
        int op = t >> 1;
        const __half* Wp = op ? W2 : W;
        int kt = (t & 1) * BK;
        uint32_t dA = sbase + (uint32_t)buf * 2 * TILE_W * 4;
        uint32_t dB = dA + TILE_W * 4;
        if (mode == 2) {
#pragma unroll
            for (int i = 0; i < 4; i++) {
                int q = tid + i * 256;
                int r = q >> 3, ch = q & 7;
                int sI = sPair[r], dI = sPair[128 + r];
                uint4 ua = *(const uint4*)(A + (size_t)sI * D + kt + ch * 8);
                uint4 ub = *(const uint4*)(A + (size_t)dI * D + kt + ch * 8);
                __half2 o0 = __hmul2(*(__half2*)&ua.x, *(__half2*)&ub.x);
                __half2 o1 = __hmul2(*(__half2*)&ua.y, *(__half2*)&ub.y);
                __half2 o2 = __hmul2(*(__half2*)&ua.z, *(__half2*)&ub.z);
                __half2 o3 = __hmul2(*(__half2*)&ua.w, *(__half2*)&ub.w);
                uint4 o;
                o.x = *(uint32_t*)&o0; o.y = *(uint32_t*)&o1;
                o.z = *(uint32_t*)&o2; o.w = *(uint32_t*)&o3;
                *(uint4*)(smem + (size_t)buf * 2 * TILE_W + r * SAB_S + ch * 4) = o;
            }
        } else if (!(mode == 1 && op == 1)) {
#pragma unroll
            for (int i = 0; i < 4; i++) {
                int q = tid + i * 256;
                int r = q >> 3, ch = q & 7;
                int grow = blockRow + r;
                cp16(dA + (uint32_t)(r * SAB_S + ch * 4) * 4,
                     A + (size_t)grow * D + kt + ch * 8, grow < M);
            }
        }
#pragma unroll
        for (int i = 0; i < 4; i++) {
            int q = tid + i * 256;
            int r = q >> 3, ch = q & 7;
            cp16(dB + (uint32_t)(r * SAB_S + ch * 4) * 4,
                 Wp + (size_t)r * D + kt + ch * 8, true);
        }
    };

    loadTile(0, 0);
    asm volatile("cp.async.commit_group;\n");

    if (mode == 1) {
#pragma unroll 1
        for (int i = 0; i < 8; i++) {
            int r = i * 16 + (tid >> 4);
            int l = tid & 15;
            int node = blockRow + r;
            float a0 = 0.f, a1 = 0.f, a2 = 0.f, a3 = 0.f;
            float a4 = 0.f, a5 = 0.f, a6 = 0.f, a7 = 0.f;
            if (node < M) {
                int st = g_rowstart[node], dg = g_deg[node];
                for (int j = 0; j < dg; j++) {
                    int s = g_csrsrc[st + j];
                    uint4 u = *(const uint4*)(A + (size_t)s * D + l * 8);
                    float2 p0 = __half22float2(*(__half2*)&u.x);
                    float2 p1 = __half22float2(*(__half2*)&u.y);
                    float2 p2 = __half22float2(*(__half2*)&u.z);
                    float2 p3 = __half22float2(*(__half2*)&u.w);
                    a0 += p0.x; a1 += p0.y; a2 += p1.x; a3 += p1.y;
                    a4 += p2.x; a5 += p2.y; a6 += p3.x; a7 += p3.y;
                }
                float inv = 1.f / fmaxf((float)dg, 1.f);
                a0 *= inv; a1 *= inv; a2 *= inv; a3 *= inv;
                a4 *= inv; a5 *= inv; a6 *= inv; a7 *= inv;
            }
            __half2 o0 = __floats2half2_rn(a0, a1);
            __half2 o1 = __floats2half2_rn(a2, a3);
            __half2 o2 = __floats2half2_rn(a4, a5);
            __half2 o3 = __floats2half2_rn(a6, a7);
            uint4 o;
            o.x = *(uint32_t*)&o0; o.y = *(uint32_t*)&o1;
            o.z = *(uint32_t*)&o2; o.w = *(uint32_t*)&o3;
            int slab = l >> 3, ch = l & 7;
            *(uint4*)(smem + AGG_OFF + (size_t)slab * TILE_W + r * SAB_S + ch * 4) = o;
        }
    }

#pragma unroll 1
    for (int t = 0; t < 4; t++) {
        if (t >= T) break;
        int buf = t & 1;
        if (t + 1 < T) loadTile(t + 1, buf ^ 1);
        asm volatile("cp.async.commit_group;\n");
        asm volatile("cp.async.wait_group 1;\n");
        __syncthreads();

        bool aggA = (mode == 1) && ((t >> 1) == 1);
        uint32_t tAaddr = aggA
            ? sbase + (uint32_t)(AGG_OFF + (t & 1) * TILE_W) * 4
            : sbase + (uint32_t)(buf * 2 * TILE_W) * 4;
        uint32_t tBaddr = sbase + (uint32_t)(buf * 2 * TILE_W + TILE_W) * 4;
#pragma unroll
        for (int ks = 0; ks < 4; ks++) {
            int kw = ks * 8;
            uint32_t a[2][4];
#pragma unroll
            for (int mt = 0; mt < 2; mt++)
                ldsm4(a[mt][0], a[mt][1], a[mt][2], a[mt][3],
                      tAaddr + (uint32_t)(aRowOff0 + mt * 16 * SAB_S + kw) * 4);
            uint32_t b[8][2];
#pragma unroll
            for (int j = 0; j < 4; j++)
                ldsm4(b[2 * j][0], b[2 * j][1], b[2 * j + 1][0], b[2 * j + 1][1],
                      tBaddr + (uint32_t)(bRowOff0 + j * 16 * SAB_S + kw) * 4);
#pragma unroll
            for (int mt = 0; mt < 2; mt++)
#pragma unroll
                for (int nt = 0; nt < 8; nt++) {
                    asm volatile(
                        "mma.sync.aligned.m16n8k16.row.col.f32.f16.f16.f32 "
                        "{%0,%1,%2,%3}, {%4,%5,%6,%7}, {%8,%9}, {%0,%1,%2,%3};"
                        : "+f"(cAcc[mt][nt][0]), "+f"(cAcc[mt][nt][1]),
                          "+f"(cAcc[mt][nt][2]), "+f"(cAcc[mt][nt][3])
                        : "r"(a[mt][0]), "r"(a[mt][1]), "r"(a[mt][2]), "r"(a[mt][3]),
                          "r"(b[nt][0]), "r"(b[nt][1]));
                }
        }
        __syncthreads();
    }

    if (probOut != nullptr) {
        float d0[4] = {0.f, 0.f, 0.f, 0.f};
        float d1[4] = {0.f, 0.f, 0.f, 0.f};
#pragma unroll
        for (int mt = 0; mt < 2; mt++) {
#pragma unroll
            for (int nt = 0; nt < 8; nt++) {
                int col = wc * 64 + nt * 8 + lr * 2;
                float bias0 = bias[col], bias1 = bias[col + 1];
                float w20 = Wp2[col * 2 + 0],       w21 = Wp2[col * 2 + 1];
                float w30 = Wp2[(col + 1) * 2 + 0], w31 = Wp2[(col + 1) * 2 + 1];
                float v0 = fmaxf(cAcc[mt][nt][0] + bias0, 0.f);
                float v1 = fmaxf(cAcc[mt][nt][1] + bias1, 0.f);
                float v2 = fmaxf(cAcc[mt][nt][2] + bias0, 0.f);
                float v3 = fmaxf(cAcc[mt][nt][3] + bias1, 0.f);
                d0[mt * 2 + 0] += v0 * w20 + v1 * w30;
                d1[mt * 2 + 0] += v0 * w21 + v1 * w31;
                d0[mt * 2 + 1] += v2 * w20 + v3 * w30;
                d1[mt * 2 + 1] += v2 * w21 + v3 * w31;
            }
        }
#pragma unroll
        for (int s = 0; s < 4; s++) {
            d0[s] += __shfl_xor_sync(0xffffffffu, d0[s], 1);
            d0[s] += __shfl_xor_sync(0xffffffffu, d0[s], 2);
            d1[s] += __shfl_xor_sync(0xffffffffu, d1[s], 1);
            d1[s] += __shfl_xor_sync(0xffffffffu, d1[s], 2);
        }
        float* sred = (float*)smem;
        if (lr == 0) {
#pragma unroll
            for (int s = 0; s < 4; s++) {
                int mt = s >> 1, half = s & 1;
                int rowL = wr * 32 + mt * 16 + half * 8 + lq;
                sred[wc * 256 + rowL * 2 + 0] = d0[s];
                sred[wc * 256 + rowL * 2 + 1] = d1[s];
            }
        }
        __syncthreads();
        if (tid < 128) {
            int grow = blockRow + tid;
            if (grow < M) {
                float D0 = sred[tid * 2 + 0] + sred[256 + tid * 2 + 0] + bp2[0];
                float D1 = sred[tid * 2 + 1] + sred[256 + tid * 2 + 1] + bp2[1];
                float mx = fmaxf(D0, D1);
                float e0 = expf(D0 - mx), e1 = expf(D1 - mx);
                probOut[grow] = e1 / (e0 + e1);
            }
        }
        return;
    }

#pragma unroll
    for (int mt = 0; mt < 2; mt++) {
#pragma unroll
        for (int nt = 0; nt < 8; nt++) {
            int col = wc * 64 + nt * 8 + lr * 2;
            float bias0 = bias[col], bias1 = bias[col + 1];
            int r0 = blockRow + wr * 32 + mt * 16 + lq;
            if (r0 < M) {
                float o0 = cAcc[mt][nt][0] + bias0;
                float o1 = cAcc[mt][nt][1] + bias1;
                if (doRelu) { o0 = fmaxf(o0, 0.f); o1 = fmaxf(o1, 0.f); }
                __half2 h = __floats2half2_rn(o0, o1);
                *(uint32_t*)(C + (size_t)r0 * D + col) = *(uint32_t*)&h;
            }
            int r1 = r0 + 8;
            if (r1 < M) {
                float o2 = cAcc[mt][nt][2] + bias0;
                float o3 = cAcc[mt][nt][3] + bias1;
                if (doRelu) { o2 = fmaxf(o2, 0.f); o3 = fmaxf(o3, 0.f); }
                __half2 h = __floats2half2_rn(o2, o3);
                *(uint32_t*)(C + (size_t)r1 * D + col) = *(uint32_t*)&h;
            }
        }
    }
}

// ---------------- launch ----------------------------------------------------
extern "C" void kernel_launch(void* const* d_in, const int* in_sizes, int n_in,
                              void* d_out, int out_size) {
    const float* x   = (const float*)d_in[0];
    const int* src   = (const int*)d_in[1];
    const int* dst   = (const int*)d_in[2];
    const int* ps    = (const int*)d_in[3];
    const int* pd    = (const int*)d_in[4];
    const int* ns    = (const int*)d_in[5];
    const int* nd    = (const int*)d_in[6];
    const float* Ws0 = (const float*)d_in[7];
    const float* Wn0 = (const float*)d_in[8];
    const float* b0  = (const float*)d_in[9];
    const float* Ws1 = (const float*)d_in[10];
    const float* Wn1 = (const float*)d_in[11];
    const float* b1  = (const float*)d_in[12];
    const float* Ws2 = (const float*)d_in[13];
    const float* Wn2 = (const float*)d_in[14];
    const float* b2  = (const float*)d_in[15];
    const float* Wp0 = (const float*)d_in[16];
    const float* bp0 = (const float*)d_in[17];
    const float* Wp1 = (const float*)d_in[18];
    const float* bp1 = (const float*)d_in[19];
    const float* Wp2 = (const float*)d_in[20];
    const float* bp2 = (const float*)d_in[21];

    int N = in_sizes[0] / D;
    int E = in_sizes[1];
    int P = in_sizes[3];
    float* out = (float*)d_out;

    __half *hA, *hB, *z2, *wcb;
    cudaGetSymbolAddress((void**)&hA, g_hA);
    cudaGetSymbolAddress((void**)&hB, g_hB);
    cudaGetSymbolAddress((void**)&z2, g_z2);
    cudaGetSymbolAddress((void**)&wcb, g_wc);

    cudaFuncSetAttribute(gemm_tc_k, cudaFuncAttributeMaxDynamicSharedMemorySize, GEMM_SMEM);

    const __half* wc0 = wcb;
    const __half* wc1 = wcb + 1 * WELEM;
    const __half* wc2 = wcb + 2 * WELEM;
    const __half* wc3 = wcb + 3 * WELEM;
    const __half* wc4 = wcb + 4 * WELEM;
    const __half* wc5 = wcb + 5 * WELEM;
    const __half* wc6 = wcb + 6 * WELEM;
    const __half* wc7 = wcb + 7 * WELEM;

    WPtrs wp;
    wp.p[0] = Ws0; wp.p[1] = Wn0; wp.p[2] = Ws1; wp.p[3] = Wn1;
    wp.p[4] = Ws2; wp.p[5] = Wn2; wp.p[6] = Wp0; wp.p[7] = Wp1;

    int nb = (N + 511) / 512;
    int gemmBlocksN = (N + 127) / 128;

    convw_k<<<dim3((WELEM + 255) / 256, 8), 256>>>(wp, wcb);
    convx_k<<<(N * D + 255) / 256, 256>>>(x, hB, N * D);
    zero_k<<<(N + 255) / 256, 256>>>(N);
    hist_k<<<(E + 255) / 256, 256>>>(dst, E);
    scan1_k<<<nb, 512>>>(N);
    scan2_k<<<1, 256>>>(nb);
    scan3_k<<<(N + 255) / 256, 256>>>(N);
    scatter_k<<<(E + 255) / 256, 256>>>(src, dst, E);

    // layer 0: hA = relu(xc@Ws0 + agg(xc)@Wn0 + b0)   [mode 1]
    gemm_tc_k<<<gemmBlocksN, 256, GEMM_SMEM>>>(hB, wc0, wc1, b0, hA, N, 1, 1,
        nullptr, nullptr, nullptr, nullptr, 0, nullptr, nullptr, nullptr);
    // layer 1: hB = relu(hA@Ws1 + agg(hA)@Wn1 + b1)
    gemm_tc_k<<<gemmBlocksN, 256, GEMM_SMEM>>>(hA, wc2, wc3, b1, hB, N, 1, 1,
        nullptr, nullptr, nullptr, nullptr, 0, nullptr, nullptr, nullptr);
    // layer 2: hA = hB@Ws2 + agg(hB)@Wn2 + b2
    gemm_tc_k<<<gemmBlocksN, 256, GEMM_SMEM>>>(hB, wc4, wc5, b2, hA, N, 0, 1,
        nullptr, nullptr, nullptr, nullptr, 0, nullptr, nullptr, nullptr);

    // predictor
    int M2 = 2 * P;
    int gemmBlocksP = (M2 + 127) / 128;
    // G1 (mode 2): z2 = relu((hA[s]*hA[d])@Wp0 + bp0)
    gemm_tc_k<<<gemmBlocksP, 256, GEMM_SMEM>>>(hA, wc6, nullptr, bp0, z2, M2, 1, 2,
        ps, pd, ns, nd, P, nullptr, nullptr, nullptr);
    // G2 (mode 0 + probOut): out = softmax(relu(z2@Wp1+bp1)@Wp2+bp2)[:,1]
    gemm_tc_k<<<gemmBlocksP, 256, GEMM_SMEM>>>(z2, wc7, nullptr, bp1, nullptr, M2, 1, 0,
        nullptr, nullptr, nullptr, nullptr, 0, out, Wp2, bp2);
}

// round 14
// speedup vs baseline: 1.0371x; 1.0371x over previous
#include <cuda_runtime.h>
#include <cuda_fp16.h>
#include <math.h>
#include <stdint.h>

#define D 128
#define NMAX 100000
#define EMAX 800000
#define PMAX 100000
#define WELEM 16384

// ---------------- scratch (device globals; no allocation allowed) ----------
__device__ __align__(16) __half g_hA[NMAX * D];
__device__ __align__(16) __half g_hB[NMAX * D];   // holds half(x) for layer 0
__device__ __align__(16) __half g_hn[NMAX * D];
__device__ __align__(16) __half g_z2[2 * PMAX * D];
__device__ __align__(16) __half g_wc[8 * WELEM];  // weights: half, transposed [n][k]
__device__ int   g_deg[NMAX];
__device__ int   g_rowstart[NMAX];
__device__ int   g_cursor[NMAX];
__device__ int   g_csrsrc[EMAX];
__device__ int   g_bsum[256];
__device__ int   g_boff[256];

// ---------------- operand pre-conversion -----------------------------------
struct WPtrs { const float* p[8]; };

__global__ void convw_k(WPtrs w, __half* out) {
    int m = blockIdx.y;
    int i = blockIdx.x * 256 + threadIdx.x;
    if (i < WELEM) {
        int k = i >> 7, n = i & 127;
        out[m * WELEM + n * 128 + k] = __float2half_rn(w.p[m][i]);
    }
}

__global__ void convx_k(const float* __restrict__ in, __half* __restrict__ out, int n) {
    int i = blockIdx.x * 256 + threadIdx.x;
    if (i < n) out[i] = __float2half_rn(in[i]);
}

// ---------------- CSR build ------------------------------------------------
__global__ void zero_k(int n) {
    int i = blockIdx.x * blockDim.x + threadIdx.x;
    if (i < n) { g_deg[i] = 0; g_cursor[i] = 0; }
}

__global__ void hist_k(const int* __restrict__ dst, int E) {
    int e = blockIdx.x * blockDim.x + threadIdx.x;
    if (e < E) atomicAdd(&g_deg[dst[e]], 1);
}

__global__ void scan1_k(int n) {
    __shared__ int s[512];
    int tid = threadIdx.x;
    int i = blockIdx.x * 512 + tid;
    int v = (i < n) ? g_deg[i] : 0;
    s[tid] = v;
    __syncthreads();
    for (int off = 1; off < 512; off <<= 1) {
        int t = (tid >= off) ? s[tid - off] : 0;
        __syncthreads();
        s[tid] += t;
        __syncthreads();
    }
    if (i < n) g_rowstart[i] = s[tid] - v;
    if (tid == 511) g_bsum[blockIdx.x] = s[511];
}

__global__ void scan2_k(int nb) {
    __shared__ int s[256];
    int tid = threadIdx.x;
    int v = (tid < nb) ? g_bsum[tid] : 0;
    s[tid] = v;
    __syncthreads();
    for (int off = 1; off < 256; off <<= 1) {
        int t = (tid >= off) ? s[tid - off] : 0;
        __syncthreads();
        s[tid] += t;
        __syncthreads();
    }
    g_boff[tid] = s[tid] - v;
}

__global__ void scan3_k(int n) {
    int i = blockIdx.x * blockDim.x + threadIdx.x;
    if (i < n) g_rowstart[i] += g_boff[i >> 9];
}

__global__ void scatter_k(const int* __restrict__ src, const int* __restrict__ dst, int E) {
    int e = blockIdx.x * blockDim.x + threadIdx.x;
    if (e >= E) return;
    int d = dst[e];
    int p = atomicAdd(&g_cursor[d], 1);
    g_csrsrc[g_rowstart[d] + p] = src[e];
}

// ---------------- mean aggregation: 16 lanes/node, uint4 loads -------------
__global__ void agg_k(const __half* __restrict__ h, __half* __restrict__ hn, int n) {
    int t = blockIdx.x * blockDim.x + threadIdx.x;
    int node = t >> 4, l = t & 15;
    if (node >= n) return;
    int st = g_rowstart[node], d = g_deg[node];
    float a0 = 0.f, a1 = 0.f, a2 = 0.f, a3 = 0.f;
    float a4 = 0.f, a5 = 0.f, a6 = 0.f, a7 = 0.f;
    for (int j = 0; j < d; j++) {
        int s = g_csrsrc[st + j];
        uint4 u = *(const uint4*)(h + (size_t)s * D + l * 8);
        float2 p0 = __half22float2(*(__half2*)&u.x);
        float2 p1 = __half22float2(*(__half2*)&u.y);
        float2 p2 = __half22float2(*(__half2*)&u.z);
        float2 p3 = __half22float2(*(__half2*)&u.w);
        a0 += p0.x; a1 += p0.y; a2 += p1.x; a3 += p1.y;
        a4 += p2.x; a5 += p2.y; a6 += p3.x; a7 += p3.y;
    }
    float inv = 1.f / fmaxf((float)d, 1.f);
    __half2 o0 = __floats2half2_rn(a0 * inv, a1 * inv);
    __half2 o1 = __floats2half2_rn(a2 * inv, a3 * inv);
    __half2 o2 = __floats2half2_rn(a4 * inv, a5 * inv);
    __half2 o3 = __floats2half2_rn(a6 * inv, a7 * inv);
    uint4 o;
    o.x = *(uint32_t*)&o0; o.y = *(uint32_t*)&o1;
    o.z = *(uint32_t*)&o2; o.w = *(uint32_t*)&o3;
    *(uint4*)(hn + (size_t)node * D + l * 8) = o;
}

// ---------------- fp16 tensor-core GEMM (round-12 core + pair loader) ------
// 128x128 tile, 8 warps 4x2 (warp 32x64), BK=64, cp.async 2-buffer, ldmatrix.
// A2 != null : dual GEMM  C = act(A@W + A2@W2 + bias)
// pairMode   : A rows are hA[s]*hA[d] built in the loader (single op)
// probOut    : fused bias+relu+@Wp2+bp2+softmax[:,1] epilogue
#define BK 64
#define SAB_S 36
#define TILE_W (128 * SAB_S)
#define PAIR_OFF (4 * TILE_W)                     // word offset of pair table
#define GEMM_SMEM (4 * TILE_W * 4 + 1024)         // 74752 bytes

__device__ __forceinline__ void cp16(uint32_t dst, const void* src, bool pred) {
    int sz = pred ? 16 : 0;
    asm volatile("cp.async.cg.shared.global [%0], [%1], 16, %2;\n"
                 :: "r"(dst), "l"(src), "r"(sz));
}

__device__ __forceinline__ void ldsm4(uint32_t& r0, uint32_t& r1, uint32_t& r2,
                                      uint32_t& r3, uint32_t addr) {
    asm volatile("ldmatrix.sync.aligned.m8n8.x4.shared.b16 {%0,%1,%2,%3}, [%4];"
                 : "=r"(r0), "=r"(r1), "=r"(r2), "=r"(r3) : "r"(addr));
}

__global__ void __launch_bounds__(256) gemm_tc_k(
    const __half* __restrict__ A, const __half* __restrict__ A2,
    const __half* __restrict__ W, const __half* __restrict__ W2,
    const float* __restrict__ bias, __half* __restrict__ C,
    int M, int doRelu, int pairMode,
    const int* __restrict__ ps, const int* __restrict__ pd,
    const int* __restrict__ ns, const int* __restrict__ nd, int Pp,
    float* __restrict__ probOut,
    const float* __restrict__ Wp2, const float* __restrict__ bp2)
{
    extern __shared__ uint32_t smem[];
    int tid = threadIdx.x;
    int lane = tid & 31;
    int w = tid >> 5;
    int wr = w >> 1, wc = w & 1;
    int blockRow = blockIdx.x * 128;
    int lq = lane >> 2;
    int lr = lane & 3;

    uint32_t sbase = (uint32_t)__cvta_generic_to_shared(smem);
    int* sPair = (int*)(smem + PAIR_OFF);

    int T = (A2 != nullptr) ? 4 : 2;

    int aRowOff0 = (wr * 32 + (lane & 7) + ((lane >> 3) & 1) * 8) * SAB_S
                 + (lane >> 4) * 4;
    int bRowOff0 = (wc * 64 + ((lane >> 4) & 1) * 8 + (lane & 7)) * SAB_S
                 + ((lane >> 3) & 1) * 4;

    float cAcc[2][8][4];
#pragma unroll
    for (int mt = 0; mt < 2; mt++)
#pragma unroll
        for (int nt = 0; nt < 8; nt++)
#pragma unroll
            for (int i = 0; i < 4; i++) cAcc[mt][nt][i] = 0.f;

    if (pairMode) {
        if (tid < 128) {
            int row = blockRow + tid;
            int s = 0, dd = 0;
            if (row < M) {
                if (row < Pp) { s = ps[row]; dd = pd[row]; }
                else          { s = ns[row - Pp]; dd = nd[row - Pp]; }
            }
            sPair[tid] = s;
            sPair[128 + tid] = dd;
        }
        __syncthreads();
    }

    auto loadTile = [&](int t, int buf) {
        const __half* Ap = (t >> 1) ? A2 : A;
        const __half* Wp = (t >> 1) ? W2 : W;
        int kt = (t & 1) * BK;
        uint32_t dA = sbase + (uint32_t)buf * 2 * TILE_W * 4;
        uint32_t dB = dA + TILE_W * 4;
        if (pairMode) {
#pragma unroll
            for (int i = 0; i < 4; i++) {
                int q = tid + i * 256;
                int r = q >> 3, ch = q & 7;
                int sI = sPair[r], dI = sPair[128 + r];
                uint4 ua = *(const uint4*)(A + (size_t)sI * D + kt + ch * 8);
                uint4 ub = *(const uint4*)(A + (size_t)dI * D + kt + ch * 8);
                __half2 o0 = __hmul2(*(__half2*)&ua.x, *(__half2*)&ub.x);
                __half2 o1 = __hmul2(*(__half2*)&ua.y, *(__half2*)&ub.y);
                __half2 o2 = __hmul2(*(__half2*)&ua.z, *(__half2*)&ub.z);
                __half2 o3 = __hmul2(*(__half2*)&ua.w, *(__half2*)&ub.w);
                uint4 o;
                o.x = *(uint32_t*)&o0; o.y = *(uint32_t*)&o1;
                o.z = *(uint32_t*)&o2; o.w = *(uint32_t*)&o3;
                *(uint4*)(smem + (size_t)buf * 2 * TILE_W + r * SAB_S + ch * 4) = o;
            }
        } else {
#pragma unroll
            for (int i = 0; i < 4; i++) {
                int q = tid + i * 256;
                int r = q >> 3, ch = q & 7;
                int grow = blockRow + r;
                cp16(dA + (uint32_t)(r * SAB_S + ch * 4) * 4,
                     Ap + (size_t)grow * D + kt + ch * 8, grow < M);
            }
        }
#pragma unroll
        for (int i = 0; i < 4; i++) {
            int q = tid + i * 256;
            int r = q >> 3, ch = q & 7;
            cp16(dB + (uint32_t)(r * SAB_S + ch * 4) * 4,
                 Wp + (size_t)r * D + kt + ch * 8, true);
        }
    };

    loadTile(0, 0);
    asm volatile("cp.async.commit_group;\n");

#pragma unroll 1
    for (int t = 0; t < 4; t++) {
        if (t >= T) break;
        int buf = t & 1;
        if (t + 1 < T) loadTile(t + 1, buf ^ 1);
        asm volatile("cp.async.commit_group;\n");
        asm volatile("cp.async.wait_group 1;\n");
        __syncthreads();

        uint32_t tAaddr = sbase + (uint32_t)(buf * 2 * TILE_W) * 4;
        uint32_t tBaddr = tAaddr + TILE_W * 4;
#pragma unroll
        for (int ks = 0; ks < 4; ks++) {
            int kw = ks * 8;
            uint32_t a[2][4];
#pragma unroll
            for (int mt = 0; mt < 2; mt++)
                ldsm4(a[mt][0], a[mt][1], a[mt][2], a[mt][3],
                      tAaddr + (uint32_t)(aRowOff0 + mt * 16 * SAB_S + kw) * 4);
            uint32_t b[8][2];
#pragma unroll
            for (int j = 0; j < 4; j++)
                ldsm4(b[2 * j][0], b[2 * j][1], b[2 * j + 1][0], b[2 * j + 1][1],
                      tBaddr + (uint32_t)(bRowOff0 + j * 16 * SAB_S + kw) * 4);
#pragma unroll
            for (int mt = 0; mt < 2; mt++)
#pragma unroll
                for (int nt = 0; nt < 8; nt++) {
                    asm volatile(
                        "mma.sync.aligned.m16n8k16.row.col.f32.f16.f16.f32 "
                        "{%0,%1,%2,%3}, {%4,%5,%6,%7}, {%8,%9}, {%0,%1,%2,%3};"
                        : "+f"(cAcc[mt][nt][0]), "+f"(cAcc[mt][nt][1]),
                          "+f"(cAcc[mt][nt][2]), "+f"(cAcc[mt][nt][3])
                        : "r"(a[mt][0]), "r"(a[mt][1]), "r"(a[mt][2]), "r"(a[mt][3]),
                          "r"(b[nt][0]), "r"(b[nt][1]));
                }
        }
        __syncthreads();
    }

    // ======== probOut mode: fused bias+relu+Wp2 dot+softmax ========
    if (probOut != nullptr) {
        float d0[4] = {0.f, 0.f, 0.f, 0.f};
        float d1[4] = {0.f, 0.f, 0.f, 0.f};
#pragma unroll
        for (int mt = 0; mt < 2; mt++) {
#pragma unroll
            for (int nt = 0; nt < 8; nt++) {
                int col = wc * 64 + nt * 8 + lr * 2;
                float bias0 = bias[col], bias1 = bias[col + 1];
                float w20 = Wp2[col * 2 + 0],       w21 = Wp2[col * 2 + 1];
                float w30 = Wp2[(col + 1) * 2 + 0], w31 = Wp2[(col + 1) * 2 + 1];
                float v0 = fmaxf(cAcc[mt][nt][0] + bias0, 0.f);
                float v1 = fmaxf(cAcc[mt][nt][1] + bias1, 0.f);
                float v2 = fmaxf(cAcc[mt][nt][2] + bias0, 0.f);
                float v3 = fmaxf(cAcc[mt][nt][3] + bias1, 0.f);
                d0[mt * 2 + 0] += v0 * w20 + v1 * w30;
                d1[mt * 2 + 0] += v0 * w21 + v1 * w31;
                d0[mt * 2 + 1] += v2 * w20 + v3 * w30;
                d1[mt * 2 + 1] += v2 * w21 + v3 * w31;
            }
        }
#pragma unroll
        for (int s = 0; s < 4; s++) {
            d0[s] += __shfl_xor_sync(0xffffffffu, d0[s], 1);
            d0[s] += __shfl_xor_sync(0xffffffffu, d0[s], 2);
            d1[s] += __shfl_xor_sync(0xffffffffu, d1[s], 1);
            d1[s] += __shfl_xor_sync(0xffffffffu, d1[s], 2);
        }
        float* sred = (float*)smem;
        if (lr == 0) {
#pragma unroll
            for (int s = 0; s < 4; s++) {
                int mt = s >> 1, half = s & 1;
                int rowL = wr * 32 + mt * 16 + half * 8 + lq;
                sred[wc * 256 + rowL * 2 + 0] = d0[s];
                sred[wc * 256 + rowL * 2 + 1] = d1[s];
            }
        }
        __syncthreads();
        if (tid < 128) {
            int grow = blockRow + tid;
            if (grow < M) {
                float D0 = sred[tid * 2 + 0] + sred[256 + tid * 2 + 0] + bp2[0];
                float D1 = sred[tid * 2 + 1] + sred[256 + tid * 2 + 1] + bp2[1];
                float mx = fmaxf(D0, D1);
                float e0 = expf(D0 - mx), e1 = expf(D1 - mx);
                probOut[grow] = e1 / (e0 + e1);
            }
        }
        return;
    }

    // ======== normal epilogue: bias + [relu] -> half C ========
#pragma unroll
    for (int mt = 0; mt < 2; mt++) {
#pragma unroll
        for (int nt = 0; nt < 8; nt++) {
            int col = wc * 64 + nt * 8 + lr * 2;
            float bias0 = bias[col], bias1 = bias[col + 1];
            int r0 = blockRow + wr * 32 + mt * 16 + lq;
            if (r0 < M) {
                float o0 = cAcc[mt][nt][0] + bias0;
                float o1 = cAcc[mt][nt][1] + bias1;
                if (doRelu) { o0 = fmaxf(o0, 0.f); o1 = fmaxf(o1, 0.f); }
                __half2 h = __floats2half2_rn(o0, o1);
                *(uint32_t*)(C + (size_t)r0 * D + col) = *(uint32_t*)&h;
            }
            int r1 = r0 + 8;
            if (r1 < M) {
                float o2 = cAcc[mt][nt][2] + bias0;
                float o3 = cAcc[mt][nt][3] + bias1;
                if (doRelu) { o2 = fmaxf(o2, 0.f); o3 = fmaxf(o3, 0.f); }
                __half2 h = __floats2half2_rn(o2, o3);
                *(uint32_t*)(C + (size_t)r1 * D + col) = *(uint32_t*)&h;
            }
        }
    }
}

// ---------------- launch ----------------------------------------------------
extern "C" void kernel_launch(void* const* d_in, const int* in_sizes, int n_in,
                              void* d_out, int out_size) {
    const float* x   = (const float*)d_in[0];
    const int* src   = (const int*)d_in[1];
    const int* dst   = (const int*)d_in[2];
    const int* ps    = (const int*)d_in[3];
    const int* pd    = (const int*)d_in[4];
    const int* ns    = (const int*)d_in[5];
    const int* nd    = (const int*)d_in[6];
    const float* Ws0 = (const float*)d_in[7];
    const float* Wn0 = (const float*)d_in[8];
    const float* b0  = (const float*)d_in[9];
    const float* Ws1 = (const float*)d_in[10];
    const float* Wn1 = (const float*)d_in[11];
    const float* b1  = (const float*)d_in[12];
    const float* Ws2 = (const float*)d_in[13];
    const float* Wn2 = (const float*)d_in[14];
    const float* b2  = (const float*)d_in[15];
    const float* Wp0 = (const float*)d_in[16];
    const float* bp0 = (const float*)d_in[17];
    const float* Wp1 = (const float*)d_in[18];
    const float* bp1 = (const float*)d_in[19];
    const float* Wp2 = (const float*)d_in[20];
    const float* bp2 = (const float*)d_in[21];

    int N = in_sizes[0] / D;
    int E = in_sizes[1];
    int P = in_sizes[3];
    float* out = (float*)d_out;

    __half *hA, *hB, *hn, *z2, *wcb;
    cudaGetSymbolAddress((void**)&hA, g_hA);
    cudaGetSymbolAddress((void**)&hB, g_hB);
    cudaGetSymbolAddress((void**)&hn, g_hn);
    cudaGetSymbolAddress((void**)&z2, g_z2);
    cudaGetSymbolAddress((void**)&wcb, g_wc);

    cudaFuncSetAttribute(gemm_tc_k, cudaFuncAttributeMaxDynamicSharedMemorySize, GEMM_SMEM);

    const __half* wc0 = wcb;
    const __half* wc1 = wcb + 1 * WELEM;
    const __half* wc2 = wcb + 2 * WELEM;
    const __half* wc3 = wcb + 3 * WELEM;
    const __half* wc4 = wcb + 4 * WELEM;
    const __half* wc5 = wcb + 5 * WELEM;
    const __half* wc6 = wcb + 6 * WELEM;
    const __half* wc7 = wcb + 7 * WELEM;

    WPtrs wp;
    wp.p[0] = Ws0; wp.p[1] = Wn0; wp.p[2] = Ws1; wp.p[3] = Wn1;
    wp.p[4] = Ws2; wp.p[5] = Wn2; wp.p[6] = Wp0; wp.p[7] = Wp1;

    int nb = (N + 511) / 512;
    int aggBlocks  = (N * 16 + 255) / 256;
    int gemmBlocksN = (N + 127) / 128;

    convw_k<<<dim3((WELEM + 255) / 256, 8), 256>>>(wp, wcb);
    convx_k<<<(N * D + 255) / 256, 256>>>(x, hB, N * D);
    zero_k<<<(N + 255) / 256, 256>>>(N);
    hist_k<<<(E + 255) / 256, 256>>>(dst, E);
    scan1_k<<<nb, 512>>>(N);
    scan2_k<<<1, 256>>>(nb);
    scan3_k<<<(N + 255) / 256, 256>>>(N);
    scatter_k<<<(E + 255) / 256, 256>>>(src, dst, E);

    // layer 0: hA = relu(xc@Ws0 + agg(xc)@Wn0 + b0)  [dual]
    agg_k<<<aggBlocks, 256>>>(hB, hn, N);
    gemm_tc_k<<<gemmBlocksN, 256, GEMM_SMEM>>>(hB, hn, wc0, wc1, b0, hA, N, 1, 0,
        nullptr, nullptr, nullptr, nullptr, 0, nullptr, nullptr, nullptr);
    // layer 1: hB = relu(hA@Ws1 + agg(hA)@Wn1 + b1)  [dual]
    agg_k<<<aggBlocks, 256>>>(hA, hn, N);
    gemm_tc_k<<<gemmBlocksN, 256, GEMM_SMEM>>>(hA, hn, wc2, wc3, b1, hB, N, 1, 0,
        nullptr, nullptr, nullptr, nullptr, 0, nullptr, nullptr, nullptr);
    // layer 2: hA = hB@Ws2 + agg(hB)@Wn2 + b2        [dual, no act]
    agg_k<<<aggBlocks, 256>>>(hB, hn, N);
    gemm_tc_k<<<gemmBlocksN, 256, GEMM_SMEM>>>(hB, hn, wc4, wc5, b2, hA, N, 0, 0,
        nullptr, nullptr, nullptr, nullptr, 0, nullptr, nullptr, nullptr);

    // predictor
    int M2 = 2 * P;
    int gemmBlocksP = (M2 + 127) / 128;
    // G1 (pair mode): z2 = relu((hA[s]*hA[d])@Wp0 + bp0)
    gemm_tc_k<<<gemmBlocksP, 256, GEMM_SMEM>>>(hA, nullptr, wc6, nullptr, bp0, z2,
        M2, 1, 1, ps, pd, ns, nd, P, nullptr, nullptr, nullptr);
    // G2 (probOut fused): out = softmax(relu(z2@Wp1+bp1)@Wp2+bp2)[:,1]
    gemm_tc_k<<<gemmBlocksP, 256, GEMM_SMEM>>>(z2, nullptr, wc7, nullptr, bp1, nullptr,
        M2, 1, 0, nullptr, nullptr, nullptr, nullptr, 0, out, Wp2, bp2);
}

// round 15
// speedup vs baseline: 1.0959x; 1.0566x over previous
#include <cuda_runtime.h>
#include <cuda_fp16.h>
#include <math.h>
#include <stdint.h>

#define D 128
#define NMAX 100000
#define EMAX 800000
#define PMAX 100000
#define WELEM 16384

// ---------------- scratch (device globals; no allocation allowed) ----------
__device__ __align__(16) __half g_hA[NMAX * D];
__device__ __align__(16) __half g_hB[NMAX * D];   // holds half(x) for layer 0
__device__ __align__(16) __half g_hn[NMAX * D];
__device__ __align__(16) __half g_z[2 * PMAX * D];   // layer-0 self acc, then predictor z
__device__ __align__(16) __half g_z2[2 * PMAX * D];
__device__ __align__(16) __half g_wc[8 * WELEM];  // weights: half, transposed [n][k]
__device__ int   g_deg[NMAX];
__device__ int   g_rowstart[NMAX];
__device__ int   g_cursor[NMAX];
__device__ int   g_csrsrc[EMAX];
__device__ int   g_bsum[256];
__device__ int   g_boff[256];

// ---------------- operand pre-conversion -----------------------------------
struct WPtrs { const float* p[8]; };

__global__ void convw_k(WPtrs w, __half* out) {
    int m = blockIdx.y;
    int i = blockIdx.x * 256 + threadIdx.x;
    if (i < WELEM) {
        int k = i >> 7, n = i & 127;
        out[m * WELEM + n * 128 + k] = __float2half_rn(w.p[m][i]);
    }
}

__global__ void convx_k(const float* __restrict__ in, __half* __restrict__ out, int n) {
    int i = blockIdx.x * 256 + threadIdx.x;
    if (i < n) out[i] = __float2half_rn(in[i]);
}

// ---------------- CSR build ------------------------------------------------
__global__ void zero_k(int n) {
    int i = blockIdx.x * blockDim.x + threadIdx.x;
    if (i < n) { g_deg[i] = 0; g_cursor[i] = 0; }
}

__global__ void hist_k(const int* __restrict__ dst, int E) {
    int e = blockIdx.x * blockDim.x + threadIdx.x;
    if (e < E) atomicAdd(&g_deg[dst[e]], 1);
}

__global__ void scan1_k(int n) {
    __shared__ int s[512];
    int tid = threadIdx.x;
    int i = blockIdx.x * 512 + tid;
    int v = (i < n) ? g_deg[i] : 0;
    s[tid] = v;
    __syncthreads();
    for (int off = 1; off < 512; off <<= 1) {
        int t = (tid >= off) ? s[tid - off] : 0;
        __syncthreads();
        s[tid] += t;
        __syncthreads();
    }
    if (i < n) g_rowstart[i] = s[tid] - v;
    if (tid == 511) g_bsum[blockIdx.x] = s[511];
}

__global__ void scan2_k(int nb) {
    __shared__ int s[256];
    int tid = threadIdx.x;
    int v = (tid < nb) ? g_bsum[tid] : 0;
    s[tid] = v;
    __syncthreads();
    for (int off = 1; off < 256; off <<= 1) {
        int t = (tid >= off) ? s[tid - off] : 0;
        __syncthreads();
        s[tid] += t;
        __syncthreads();
    }
    g_boff[tid] = s[tid] - v;
}

__global__ void scan3_k(int n) {
    int i = blockIdx.x * blockDim.x + threadIdx.x;
    if (i < n) g_rowstart[i] += g_boff[i >> 9];
}

__global__ void scatter_k(const int* __restrict__ src, const int* __restrict__ dst, int E) {
    int e = blockIdx.x * blockDim.x + threadIdx.x;
    if (e >= E) return;
    int d = dst[e];
    int p = atomicAdd(&g_cursor[d], 1);
    g_csrsrc[g_rowstart[d] + p] = src[e];
}

// ---------------- mean aggregation: 16 lanes/node, unroll-2 for MLP --------
__global__ void agg_k(const __half* __restrict__ h, __half* __restrict__ hn, int n) {
    int t = blockIdx.x * blockDim.x + threadIdx.x;
    int node = t >> 4, l = t & 15;
    if (node >= n) return;
    int st = g_rowstart[node], d = g_deg[node];
    float a0 = 0.f, a1 = 0.f, a2 = 0.f, a3 = 0.f;
    float a4 = 0.f, a5 = 0.f, a6 = 0.f, a7 = 0.f;
    int j = 0;
    for (; j + 1 < d; j += 2) {
        int s0 = g_csrsrc[st + j];
        int s1 = g_csrsrc[st + j + 1];
        uint4 u0 = *(const uint4*)(h + (size_t)s0 * D + l * 8);
        uint4 u1 = *(const uint4*)(h + (size_t)s1 * D + l * 8);
        float2 p0 = __half22float2(*(__half2*)&u0.x);
        float2 p1 = __half22float2(*(__half2*)&u0.y);
        float2 p2 = __half22float2(*(__half2*)&u0.z);
        float2 p3 = __half22float2(*(__half2*)&u0.w);
        a0 += p0.x; a1 += p0.y; a2 += p1.x; a3 += p1.y;
        a4 += p2.x; a5 += p2.y; a6 += p3.x; a7 += p3.y;
        float2 q0 = __half22float2(*(__half2*)&u1.x);
        float2 q1 = __half22float2(*(__half2*)&u1.y);
        float2 q2 = __half22float2(*(__half2*)&u1.z);
        float2 q3 = __half22float2(*(__half2*)&u1.w);
        a0 += q0.x; a1 += q0.y; a2 += q1.x; a3 += q1.y;
        a4 += q2.x; a5 += q2.y; a6 += q3.x; a7 += q3.y;
    }
    if (j < d) {
        int s0 = g_csrsrc[st + j];
        uint4 u0 = *(const uint4*)(h + (size_t)s0 * D + l * 8);
        float2 p0 = __half22float2(*(__half2*)&u0.x);
        float2 p1 = __half22float2(*(__half2*)&u0.y);
        float2 p2 = __half22float2(*(__half2*)&u0.z);
        float2 p3 = __half22float2(*(__half2*)&u0.w);
        a0 += p0.x; a1 += p0.y; a2 += p1.x; a3 += p1.y;
        a4 += p2.x; a5 += p2.y; a6 += p3.x; a7 += p3.y;
    }
    float inv = 1.f / fmaxf((float)d, 1.f);
    __half2 o0 = __floats2half2_rn(a0 * inv, a1 * inv);
    __half2 o1 = __floats2half2_rn(a2 * inv, a3 * inv);
    __half2 o2 = __floats2half2_rn(a4 * inv, a5 * inv);
    __half2 o3 = __floats2half2_rn(a6 * inv, a7 * inv);
    uint4 o;
    o.x = *(uint32_t*)&o0; o.y = *(uint32_t*)&o1;
    o.z = *(uint32_t*)&o2; o.w = *(uint32_t*)&o3;
    *(uint4*)(hn + (size_t)node * D + l * 8) = o;
}

// ---------------- fp16 tensor-core GEMM (round-12 core) ---------------------
// 128x128 tile, 8 warps 4x2 (warp 32x64), BK=64, cp.async 2-buffer, ldmatrix.
// Modes: normal C-out (bias optional, relu optional, accIn(half) optional);
//        probOut mode: fused @Wp1 result -> relu -> @Wp2+bp2 -> softmax[:,1].
#define BK 64
#define SAB_S 36
#define TILE_W (128 * SAB_S)
#define GEMM_SMEM (4 * TILE_W * 4)   // 73728

__device__ __forceinline__ void cp16(uint32_t dst, const void* src, bool pred) {
    int sz = pred ? 16 : 0;
    asm volatile("cp.async.cg.shared.global [%0], [%1], 16, %2;\n"
                 :: "r"(dst), "l"(src), "r"(sz));
}

__device__ __forceinline__ void ldsm4(uint32_t& r0, uint32_t& r1, uint32_t& r2,
                                      uint32_t& r3, uint32_t addr) {
    asm volatile("ldmatrix.sync.aligned.m8n8.x4.shared.b16 {%0,%1,%2,%3}, [%4];"
                 : "=r"(r0), "=r"(r1), "=r"(r2), "=r"(r3) : "r"(addr));
}

__global__ void __launch_bounds__(256) gemm_tc_k(
    const __half* __restrict__ A, const __half* __restrict__ A2,
    const __half* __restrict__ W, const __half* __restrict__ W2,
    const float* __restrict__ bias, __half* __restrict__ C,
    int M, int doRelu,
    const __half* __restrict__ accIn,
    float* __restrict__ probOut,
    const float* __restrict__ Wp2, const float* __restrict__ bp2)
{
    extern __shared__ uint32_t smem[];
    int tid = threadIdx.x;
    int lane = tid & 31;
    int w = tid >> 5;
    int wr = w >> 1, wc = w & 1;
    int blockRow = blockIdx.x * 128;
    int lq = lane >> 2;
    int lr = lane & 3;

    uint32_t sbase = (uint32_t)__cvta_generic_to_shared(smem);

    int T = (A2 != nullptr) ? 4 : 2;

    int aRowOff0 = (wr * 32 + (lane & 7) + ((lane >> 3) & 1) * 8) * SAB_S
                 + (lane >> 4) * 4;
    int bRowOff0 = (wc * 64 + ((lane >> 4) & 1) * 8 + (lane & 7)) * SAB_S
                 + ((lane >> 3) & 1) * 4;

    float c[2][8][4];
#pragma unroll
    for (int mt = 0; mt < 2; mt++)
#pragma unroll
        for (int nt = 0; nt < 8; nt++)
#pragma unroll
            for (int i = 0; i < 4; i++) c[mt][nt][i] = 0.f;

    auto loadTile = [&](int t, int buf) {
        const __half* Ap = (t >> 1) ? A2 : A;
        const __half* Wp = (t >> 1) ? W2 : W;
        int kt = (t & 1) * BK;
        uint32_t dA = sbase + (uint32_t)buf * 2 * TILE_W * 4;
        uint32_t dB = dA + TILE_W * 4;
#pragma unroll
        for (int i = 0; i < 4; i++) {
            int q = tid + i * 256;
            int r = q >> 3, ch = q & 7;
            int grow = blockRow + r;
            cp16(dA + (uint32_t)(r * SAB_S + ch * 4) * 4,
                 Ap + (size_t)grow * D + kt + ch * 8, grow < M);
        }
#pragma unroll
        for (int i = 0; i < 4; i++) {
            int q = tid + i * 256;
            int r = q >> 3, ch = q & 7;
            cp16(dB + (uint32_t)(r * SAB_S + ch * 4) * 4,
                 Wp + (size_t)r * D + kt + ch * 8, true);
        }
    };

    loadTile(0, 0);
    asm volatile("cp.async.commit_group;\n");

#pragma unroll 1
    for (int t = 0; t < 4; t++) {
        if (t >= T) break;
        int buf = t & 1;
        if (t + 1 < T) loadTile(t + 1, buf ^ 1);
        asm volatile("cp.async.commit_group;\n");
        asm volatile("cp.async.wait_group 1;\n");
        __syncthreads();

        uint32_t tAaddr = sbase + (uint32_t)(buf * 2 * TILE_W) * 4;
        uint32_t tBaddr = tAaddr + TILE_W * 4;
#pragma unroll
        for (int ks = 0; ks < 4; ks++) {
            int kw = ks * 8;
            uint32_t a[2][4];
#pragma unroll
            for (int mt = 0; mt < 2; mt++)
                ldsm4(a[mt][0], a[mt][1], a[mt][2], a[mt][3],
                      tAaddr + (uint32_t)(aRowOff0 + mt * 16 * SAB_S + kw) * 4);
            uint32_t b[8][2];
#pragma unroll
            for (int j = 0; j < 4; j++)
                ldsm4(b[2 * j][0], b[2 * j][1], b[2 * j + 1][0], b[2 * j + 1][1],
                      tBaddr + (uint32_t)(bRowOff0 + j * 16 * SAB_S + kw) * 4);
#pragma unroll
            for (int mt = 0; mt < 2; mt++)
#pragma unroll
                for (int nt = 0; nt < 8; nt++) {
                    asm volatile(
                        "mma.sync.aligned.m16n8k16.row.col.f32.f16.f16.f32 "
                        "{%0,%1,%2,%3}, {%4,%5,%6,%7}, {%8,%9}, {%0,%1,%2,%3};"
                        : "+f"(c[mt][nt][0]), "+f"(c[mt][nt][1]),
                          "+f"(c[mt][nt][2]), "+f"(c[mt][nt][3])
                        : "r"(a[mt][0]), "r"(a[mt][1]), "r"(a[mt][2]), "r"(a[mt][3]),
                          "r"(b[nt][0]), "r"(b[nt][1]));
                }
        }
        __syncthreads();
    }

    // ======== probOut mode: fused bias+relu+Wp2 dot+softmax ========
    if (probOut != nullptr) {
        float d0[4] = {0.f, 0.f, 0.f, 0.f};
        float d1[4] = {0.f, 0.f, 0.f, 0.f};
#pragma unroll
        for (int mt = 0; mt < 2; mt++) {
#pragma unroll
            for (int nt = 0; nt < 8; nt++) {
                int col = wc * 64 + nt * 8 + lr * 2;
                float bias0 = bias[col], bias1 = bias[col + 1];
                float w20 = Wp2[col * 2 + 0],       w21 = Wp2[col * 2 + 1];
                float w30 = Wp2[(col + 1) * 2 + 0], w31 = Wp2[(col + 1) * 2 + 1];
                float v0 = fmaxf(c[mt][nt][0] + bias0, 0.f);
                float v1 = fmaxf(c[mt][nt][1] + bias1, 0.f);
                float v2 = fmaxf(c[mt][nt][2] + bias0, 0.f);
                float v3 = fmaxf(c[mt][nt][3] + bias1, 0.f);
                d0[mt * 2 + 0] += v0 * w20 + v1 * w30;
                d1[mt * 2 + 0] += v0 * w21 + v1 * w31;
                d0[mt * 2 + 1] += v2 * w20 + v3 * w30;
                d1[mt * 2 + 1] += v2 * w21 + v3 * w31;
            }
        }
#pragma unroll
        for (int s = 0; s < 4; s++) {
            d0[s] += __shfl_xor_sync(0xffffffffu, d0[s], 1);
            d0[s] += __shfl_xor_sync(0xffffffffu, d0[s], 2);
            d1[s] += __shfl_xor_sync(0xffffffffu, d1[s], 1);
            d1[s] += __shfl_xor_sync(0xffffffffu, d1[s], 2);
        }
        float* sred = (float*)smem;
        if (lr == 0) {
#pragma unroll
            for (int s = 0; s < 4; s++) {
                int mt = s >> 1, half = s & 1;
                int rowL = wr * 32 + mt * 16 + half * 8 + lq;
                sred[wc * 256 + rowL * 2 + 0] = d0[s];
                sred[wc * 256 + rowL * 2 + 1] = d1[s];
            }
        }
        __syncthreads();
        if (tid < 128) {
            int grow = blockRow + tid;
            if (grow < M) {
                float D0 = sred[tid * 2 + 0] + sred[256 + tid * 2 + 0] + bp2[0];
                float D1 = sred[tid * 2 + 1] + sred[256 + tid * 2 + 1] + bp2[1];
                float mx = fmaxf(D0, D1);
                float e0 = expf(D0 - mx), e1 = expf(D1 - mx);
                probOut[grow] = e1 / (e0 + e1);
            }
        }
        return;
    }

    // ======== normal epilogue: [bias] + [accIn(half)] + [relu] -> half C ====
#pragma unroll
    for (int mt = 0; mt < 2; mt++) {
#pragma unroll
        for (int nt = 0; nt < 8; nt++) {
            int col = wc * 64 + nt * 8 + lr * 2;
            float bias0 = bias ? bias[col] : 0.f;
            float bias1 = bias ? bias[col + 1] : 0.f;
            int r0 = blockRow + wr * 32 + mt * 16 + lq;
            if (r0 < M) {
                float o0 = c[mt][nt][0] + bias0;
                float o1 = c[mt][nt][1] + bias1;
                if (accIn) {
                    uint32_t av = *(const uint32_t*)(accIn + (size_t)r0 * D + col);
                    float2 q = __half22float2(*(__half2*)&av);
                    o0 += q.x; o1 += q.y;
                }
                if (doRelu) { o0 = fmaxf(o0, 0.f); o1 = fmaxf(o1, 0.f); }
                __half2 h = __floats2half2_rn(o0, o1);
                *(uint32_t*)(C + (size_t)r0 * D + col) = *(uint32_t*)&h;
            }
            int r1 = r0 + 8;
            if (r1 < M) {
                float o2 = c[mt][nt][2] + bias0;
                float o3 = c[mt][nt][3] + bias1;
                if (accIn) {
                    uint32_t av = *(const uint32_t*)(accIn + (size_t)r1 * D + col);
                    float2 q = __half22float2(*(__half2*)&av);
                    o2 += q.x; o3 += q.y;
                }
                if (doRelu) { o2 = fmaxf(o2, 0.f); o3 = fmaxf(o3, 0.f); }
                __half2 h = __floats2half2_rn(o2, o3);
                *(uint32_t*)(C + (size_t)r1 * D + col) = *(uint32_t*)&h;
            }
        }
    }
}

// ---------------- predictor -------------------------------------------------
__global__ void buildz_k(const __half* __restrict__ h,
                         const int* __restrict__ ps, const int* __restrict__ pd,
                         const int* __restrict__ ns, const int* __restrict__ nd,
                         int P) {
    int t = blockIdx.x * blockDim.x + threadIdx.x;
    int row = t >> 4, l = t & 15;
    if (row >= 2 * P) return;
    int s, d;
    if (row < P) { s = ps[row]; d = pd[row]; }
    else         { s = ns[row - P]; d = nd[row - P]; }
    uint4 ua = *(const uint4*)(h + (size_t)s * D + l * 8);
    uint4 ub = *(const uint4*)(h + (size_t)d * D + l * 8);
    __half2 o0 = __hmul2(*(__half2*)&ua.x, *(__half2*)&ub.x);
    __half2 o1 = __hmul2(*(__half2*)&ua.y, *(__half2*)&ub.y);
    __half2 o2 = __hmul2(*(__half2*)&ua.z, *(__half2*)&ub.z);
    __half2 o3 = __hmul2(*(__half2*)&ua.w, *(__half2*)&ub.w);
    uint4 o;
    o.x = *(uint32_t*)&o0; o.y = *(uint32_t*)&o1;
    o.z = *(uint32_t*)&o2; o.w = *(uint32_t*)&o3;
    *(uint4*)(g_z + (size_t)row * D + l * 8) = o;
}

// ---------------- launch ----------------------------------------------------
extern "C" void kernel_launch(void* const* d_in, const int* in_sizes, int n_in,
                              void* d_out, int out_size) {
    const float* x   = (const float*)d_in[0];
    const int* src   = (const int*)d_in[1];
    const int* dst   = (const int*)d_in[2];
    const int* ps    = (const int*)d_in[3];
    const int* pd    = (const int*)d_in[4];
    const int* ns    = (const int*)d_in[5];
    const int* nd    = (const int*)d_in[6];
    const float* Ws0 = (const float*)d_in[7];
    const float* Wn0 = (const float*)d_in[8];
    const float* b0  = (const float*)d_in[9];
    const float* Ws1 = (const float*)d_in[10];
    const float* Wn1 = (const float*)d_in[11];
    const float* b1  = (const float*)d_in[12];
    const float* Ws2 = (const float*)d_in[13];
    const float* Wn2 = (const float*)d_in[14];
    const float* b2  = (const float*)d_in[15];
    const float* Wp0 = (const float*)d_in[16];
    const float* bp0 = (const float*)d_in[17];
    const float* Wp1 = (const float*)d_in[18];
    const float* bp1 = (const float*)d_in[19];
    const float* Wp2 = (const float*)d_in[20];
    const float* bp2 = (const float*)d_in[21];

    int N = in_sizes[0] / D;
    int E = in_sizes[1];
    int P = in_sizes[3];
    float* out = (float*)d_out;

    __half *hA, *hB, *hn, *z, *z2, *wcb;
    cudaGetSymbolAddress((void**)&hA, g_hA);
    cudaGetSymbolAddress((void**)&hB, g_hB);
    cudaGetSymbolAddress((void**)&hn, g_hn);
    cudaGetSymbolAddress((void**)&z,  g_z);
    cudaGetSymbolAddress((void**)&z2, g_z2);
    cudaGetSymbolAddress((void**)&wcb, g_wc);

    cudaFuncSetAttribute(gemm_tc_k, cudaFuncAttributeMaxDynamicSharedMemorySize, GEMM_SMEM);

    const __half* wc0 = wcb;
    const __half* wc1 = wcb + 1 * WELEM;
    const __half* wc2 = wcb + 2 * WELEM;
    const __half* wc3 = wcb + 3 * WELEM;
    const __half* wc4 = wcb + 4 * WELEM;
    const __half* wc5 = wcb + 5 * WELEM;
    const __half* wc6 = wcb + 6 * WELEM;
    const __half* wc7 = wcb + 7 * WELEM;

    WPtrs wp;
    wp.p[0] = Ws0; wp.p[1] = Wn0; wp.p[2] = Ws1; wp.p[3] = Wn1;
    wp.p[4] = Ws2; wp.p[5] = Wn2; wp.p[6] = Wp0; wp.p[7] = Wp1;

    int nb = (N + 511) / 512;
    int aggBlocks  = (N * 16 + 255) / 256;
    int gemmBlocksN = (N + 127) / 128;

    convw_k<<<dim3((WELEM + 255) / 256, 8), 256>>>(wp, wcb);       // 0
    convx_k<<<(N * D + 255) / 256, 256>>>(x, hB, N * D);           // 1
    zero_k<<<(N + 255) / 256, 256>>>(N);                           // 2
    // layer-0 self GEMM at slot 3 (profiled): z(half) = xc @ Ws0 (no bias)
    gemm_tc_k<<<gemmBlocksN, 256, GEMM_SMEM>>>(hB, nullptr, wc0, nullptr,
                                               nullptr, z, N, 0,
                                               nullptr, nullptr, nullptr, nullptr); // 3
    hist_k<<<(E + 255) / 256, 256>>>(dst, E);                      // 4
    scan1_k<<<nb, 512>>>(N);
    scan2_k<<<1, 256>>>(nb);
    scan3_k<<<(N + 255) / 256, 256>>>(N);
    scatter_k<<<(E + 255) / 256, 256>>>(src, dst, E);

    // layer 0 neigh: hA = relu(z + agg(xc)@Wn0 + b0)
    agg_k<<<aggBlocks, 256>>>(hB, hn, N);
    gemm_tc_k<<<gemmBlocksN, 256, GEMM_SMEM>>>(hn, nullptr, wc1, nullptr,
                                               b0, hA, N, 1,
                                               z, nullptr, nullptr, nullptr);
    // layer 1: hA -> hB (relu), dual
    agg_k<<<aggBlocks, 256>>>(hA, hn, N);
    gemm_tc_k<<<gemmBlocksN, 256, GEMM_SMEM>>>(hA, hn, wc2, wc3, b1, hB, N, 1,
                                               nullptr, nullptr, nullptr, nullptr);
    // layer 2: hB -> hA (no act), dual
    agg_k<<<aggBlocks, 256>>>(hB, hn, N);
    gemm_tc_k<<<gemmBlocksN, 256, GEMM_SMEM>>>(hB, hn, wc4, wc5, b2, hA, N, 0,
                                               nullptr, nullptr, nullptr, nullptr);

    // predictor
    int M2 = 2 * P;
    int zBlocks16 = (M2 * 16 + 255) / 256;
    int gemmBlocksP = (M2 + 127) / 128;
    buildz_k<<<zBlocks16, 256>>>(hA, ps, pd, ns, nd, P);
    // G1: z2 = relu(z @ Wp0 + bp0)
    gemm_tc_k<<<gemmBlocksP, 256, GEMM_SMEM>>>(z, nullptr, wc6, nullptr, bp0, z2,
                                               M2, 1, nullptr, nullptr, nullptr, nullptr);
    // G2 fused: out = softmax(relu(z2 @ Wp1 + bp1) @ Wp2 + bp2)[:,1]
    gemm_tc_k<<<gemmBlocksP, 256, GEMM_SMEM>>>(z2, nullptr, wc7, nullptr, bp1, nullptr,
                                               M2, 1, nullptr, out, Wp2, bp2);
}

// round 16
// speedup vs baseline: 1.1535x; 1.0526x over previous
#include <cuda_runtime.h>
#include <cuda_fp16.h>
#include <math.h>
#include <stdint.h>

#define D 128
#define NMAX 100000
#define EMAX 800000
#define PMAX 100000
#define WELEM 16384

// ---------------- scratch (device globals; no allocation allowed) ----------
__device__ __align__(16) __half g_hA[NMAX * D];
__device__ __align__(16) __half g_hB[NMAX * D];   // holds half(x) for layer 0
__device__ __align__(16) __half g_hn[NMAX * D];
__device__ __align__(16) __half g_z[2 * PMAX * D];   // predictor z
__device__ __align__(16) __half g_z2[2 * PMAX * D];
__device__ __align__(16) __half g_wc[8 * WELEM];  // weights: half, transposed [n][k]
__device__ int   g_deg[NMAX];
__device__ int   g_rowstart[NMAX];
__device__ int   g_cursor[NMAX];
__device__ int   g_csrsrc[EMAX];
__device__ int   g_bsum[256];
__device__ int   g_boff[256];

// ---------------- operand pre-conversion -----------------------------------
struct WPtrs { const float* p[8]; };

__global__ void convw_k(WPtrs w, __half* out) {
    int m = blockIdx.y;
    int i = blockIdx.x * 256 + threadIdx.x;
    if (i < WELEM) {
        int k = i >> 7, n = i & 127;
        out[m * WELEM + n * 128 + k] = __float2half_rn(w.p[m][i]);
    }
}

__global__ void convx_k(const float* __restrict__ in, __half* __restrict__ out, int n) {
    int i = blockIdx.x * 256 + threadIdx.x;
    if (i < n) out[i] = __float2half_rn(in[i]);
}

// ---------------- CSR build ------------------------------------------------
__global__ void zero_k(int n) {
    int i = blockIdx.x * blockDim.x + threadIdx.x;
    if (i < n) { g_deg[i] = 0; g_cursor[i] = 0; }
}

__global__ void hist_k(const int* __restrict__ dst, int E) {
    int e = blockIdx.x * blockDim.x + threadIdx.x;
    if (e < E) atomicAdd(&g_deg[dst[e]], 1);
}

__global__ void scan1_k(int n) {
    __shared__ int s[512];
    int tid = threadIdx.x;
    int i = blockIdx.x * 512 + tid;
    int v = (i < n) ? g_deg[i] : 0;
    s[tid] = v;
    __syncthreads();
    for (int off = 1; off < 512; off <<= 1) {
        int t = (tid >= off) ? s[tid - off] : 0;
        __syncthreads();
        s[tid] += t;
        __syncthreads();
    }
    if (i < n) g_rowstart[i] = s[tid] - v;
    if (tid == 511) g_bsum[blockIdx.x] = s[511];
}

__global__ void scan2_k(int nb) {
    __shared__ int s[256];
    int tid = threadIdx.x;
    int v = (tid < nb) ? g_bsum[tid] : 0;
    s[tid] = v;
    __syncthreads();
    for (int off = 1; off < 256; off <<= 1) {
        int t = (tid >= off) ? s[tid - off] : 0;
        __syncthreads();
        s[tid] += t;
        __syncthreads();
    }
    g_boff[tid] = s[tid] - v;
}

__global__ void scan3_k(int n) {
    int i = blockIdx.x * blockDim.x + threadIdx.x;
    if (i < n) g_rowstart[i] += g_boff[i >> 9];
}

__global__ void scatter_k(const int* __restrict__ src, const int* __restrict__ dst, int E) {
    int e = blockIdx.x * blockDim.x + threadIdx.x;
    if (e >= E) return;
    int d = dst[e];
    int p = atomicAdd(&g_cursor[d], 1);
    g_csrsrc[g_rowstart[d] + p] = src[e];
}

// ---------------- mean aggregation: 16 lanes/node, uint4 loads -------------
__global__ void agg_k(const __half* __restrict__ h, __half* __restrict__ hn, int n) {
    int t = blockIdx.x * blockDim.x + threadIdx.x;
    int node = t >> 4, l = t & 15;
    if (node >= n) return;
    int st = g_rowstart[node], d = g_deg[node];
    float a0 = 0.f, a1 = 0.f, a2 = 0.f, a3 = 0.f;
    float a4 = 0.f, a5 = 0.f, a6 = 0.f, a7 = 0.f;
    for (int j = 0; j < d; j++) {
        int s = g_csrsrc[st + j];
        uint4 u = *(const uint4*)(h + (size_t)s * D + l * 8);
        float2 p0 = __half22float2(*(__half2*)&u.x);
        float2 p1 = __half22float2(*(__half2*)&u.y);
        float2 p2 = __half22float2(*(__half2*)&u.z);
        float2 p3 = __half22float2(*(__half2*)&u.w);
        a0 += p0.x; a1 += p0.y; a2 += p1.x; a3 += p1.y;
        a4 += p2.x; a5 += p2.y; a6 += p3.x; a7 += p3.y;
    }
    float inv = 1.f / fmaxf((float)d, 1.f);
    __half2 o0 = __floats2half2_rn(a0 * inv, a1 * inv);
    __half2 o1 = __floats2half2_rn(a2 * inv, a3 * inv);
    __half2 o2 = __floats2half2_rn(a4 * inv, a5 * inv);
    __half2 o3 = __floats2half2_rn(a6 * inv, a7 * inv);
    uint4 o;
    o.x = *(uint32_t*)&o0; o.y = *(uint32_t*)&o1;
    o.z = *(uint32_t*)&o2; o.w = *(uint32_t*)&o3;
    *(uint4*)(hn + (size_t)node * D + l * 8) = o;
}

// ---------------- fp16 tensor-core GEMM (round-12 core) ---------------------
// 128x128 tile, 8 warps 4x2 (warp 32x64), BK=64, cp.async 2-buffer, ldmatrix.
// Dual GEMM via A2/W2; probOut mode fuses bias+relu+@Wp2+bp2+softmax[:,1].
#define BK 64
#define SAB_S 36
#define TILE_W (128 * SAB_S)
#define GEMM_SMEM (4 * TILE_W * 4)   // 73728

__device__ __forceinline__ void cp16(uint32_t dst, const void* src, bool pred) {
    int sz = pred ? 16 : 0;
    asm volatile("cp.async.cg.shared.global [%0], [%1], 16, %2;\n"
                 :: "r"(dst), "l"(src), "r"(sz));
}

__device__ __forceinline__ void ldsm4(uint32_t& r0, uint32_t& r1, uint32_t& r2,
                                      uint32_t& r3, uint32_t addr) {
    asm volatile("ldmatrix.sync.aligned.m8n8.x4.shared.b16 {%0,%1,%2,%3}, [%4];"
                 : "=r"(r0), "=r"(r1), "=r"(r2), "=r"(r3) : "r"(addr));
}

__global__ void __launch_bounds__(256) gemm_tc_k(
    const __half* __restrict__ A, const __half* __restrict__ A2,
    const __half* __restrict__ W, const __half* __restrict__ W2,
    const float* __restrict__ bias, __half* __restrict__ C,
    int M, int doRelu,
    float* __restrict__ probOut,
    const float* __restrict__ Wp2, const float* __restrict__ bp2)
{
    extern __shared__ uint32_t smem[];
    int tid = threadIdx.x;
    int lane = tid & 31;
    int w = tid >> 5;
    int wr = w >> 1, wc = w & 1;
    int blockRow = blockIdx.x * 128;
    int lq = lane >> 2;
    int lr = lane & 3;

    uint32_t sbase = (uint32_t)__cvta_generic_to_shared(smem);

    int T = (A2 != nullptr) ? 4 : 2;

    int aRowOff0 = (wr * 32 + (lane & 7) + ((lane >> 3) & 1) * 8) * SAB_S
                 + (lane >> 4) * 4;
    int bRowOff0 = (wc * 64 + ((lane >> 4) & 1) * 8 + (lane & 7)) * SAB_S
                 + ((lane >> 3) & 1) * 4;

    float c[2][8][4];
#pragma unroll
    for (int mt = 0; mt < 2; mt++)
#pragma unroll
        for (int nt = 0; nt < 8; nt++)
#pragma unroll
            for (int i = 0; i < 4; i++) c[mt][nt][i] = 0.f;

    auto loadTile = [&](int t, int buf) {
        const __half* Ap = (t >> 1) ? A2 : A;
        const __half* Wp = (t >> 1) ? W2 : W;
        int kt = (t & 1) * BK;
        uint32_t dA = sbase + (uint32_t)buf * 2 * TILE_W * 4;
        uint32_t dB = dA + TILE_W * 4;
#pragma unroll
        for (int i = 0; i < 4; i++) {
            int q = tid + i * 256;
            int r = q >> 3, ch = q & 7;
            int grow = blockRow + r;
            cp16(dA + (uint32_t)(r * SAB_S + ch * 4) * 4,
                 Ap + (size_t)grow * D + kt + ch * 8, grow < M);
        }
#pragma unroll
        for (int i = 0; i < 4; i++) {
            int q = tid + i * 256;
            int r = q >> 3, ch = q & 7;
            cp16(dB + (uint32_t)(r * SAB_S + ch * 4) * 4,
                 Wp + (size_t)r * D + kt + ch * 8, true);
        }
    };

    loadTile(0, 0);
    asm volatile("cp.async.commit_group;\n");

#pragma unroll 1
    for (int t = 0; t < 4; t++) {
        if (t >= T) break;
        int buf = t & 1;
        if (t + 1 < T) loadTile(t + 1, buf ^ 1);
        asm volatile("cp.async.commit_group;\n");
        asm volatile("cp.async.wait_group 1;\n");
        __syncthreads();

        uint32_t tAaddr = sbase + (uint32_t)(buf * 2 * TILE_W) * 4;
        uint32_t tBaddr = tAaddr + TILE_W * 4;
#pragma unroll
        for (int ks = 0; ks < 4; ks++) {
            int kw = ks * 8;
            uint32_t a[2][4];
#pragma unroll
            for (int mt = 0; mt < 2; mt++)
                ldsm4(a[mt][0], a[mt][1], a[mt][2], a[mt][3],
                      tAaddr + (uint32_t)(aRowOff0 + mt * 16 * SAB_S + kw) * 4);
            uint32_t b[8][2];
#pragma unroll
            for (int j = 0; j < 4; j++)
                ldsm4(b[2 * j][0], b[2 * j][1], b[2 * j + 1][0], b[2 * j + 1][1],
                      tBaddr + (uint32_t)(bRowOff0 + j * 16 * SAB_S + kw) * 4);
#pragma unroll
            for (int mt = 0; mt < 2; mt++)
#pragma unroll
                for (int nt = 0; nt < 8; nt++) {
                    asm volatile(
                        "mma.sync.aligned.m16n8k16.row.col.f32.f16.f16.f32 "
                        "{%0,%1,%2,%3}, {%4,%5,%6,%7}, {%8,%9}, {%0,%1,%2,%3};"
                        : "+f"(c[mt][nt][0]), "+f"(c[mt][nt][1]),
                          "+f"(c[mt][nt][2]), "+f"(c[mt][nt][3])
                        : "r"(a[mt][0]), "r"(a[mt][1]), "r"(a[mt][2]), "r"(a[mt][3]),
                          "r"(b[nt][0]), "r"(b[nt][1]));
                }
        }
        __syncthreads();
    }

    // ======== probOut mode: fused bias+relu+Wp2 dot+softmax ========
    if (probOut != nullptr) {
        float d0[4] = {0.f, 0.f, 0.f, 0.f};
        float d1[4] = {0.f, 0.f, 0.f, 0.f};
#pragma unroll
        for (int mt = 0; mt < 2; mt++) {
#pragma unroll
            for (int nt = 0; nt < 8; nt++) {
                int col = wc * 64 + nt * 8 + lr * 2;
                float bias0 = bias[col], bias1 = bias[col + 1];
                float w20 = Wp2[col * 2 + 0],       w21 = Wp2[col * 2 + 1];
                float w30 = Wp2[(col + 1) * 2 + 0], w31 = Wp2[(col + 1) * 2 + 1];
                float v0 = fmaxf(c[mt][nt][0] + bias0, 0.f);
                float v1 = fmaxf(c[mt][nt][1] + bias1, 0.f);
                float v2 = fmaxf(c[mt][nt][2] + bias0, 0.f);
                float v3 = fmaxf(c[mt][nt][3] + bias1, 0.f);
                d0[mt * 2 + 0] += v0 * w20 + v1 * w30;
                d1[mt * 2 + 0] += v0 * w21 + v1 * w31;
                d0[mt * 2 + 1] += v2 * w20 + v3 * w30;
                d1[mt * 2 + 1] += v2 * w21 + v3 * w31;
            }
        }
#pragma unroll
        for (int s = 0; s < 4; s++) {
            d0[s] += __shfl_xor_sync(0xffffffffu, d0[s], 1);
            d0[s] += __shfl_xor_sync(0xffffffffu, d0[s], 2);
            d1[s] += __shfl_xor_sync(0xffffffffu, d1[s], 1);
            d1[s] += __shfl_xor_sync(0xffffffffu, d1[s], 2);
        }
        float* sred = (float*)smem;
        if (lr == 0) {
#pragma unroll
            for (int s = 0; s < 4; s++) {
                int mt = s >> 1, half = s & 1;
                int rowL = wr * 32 + mt * 16 + half * 8 + lq;
                sred[wc * 256 + rowL * 2 + 0] = d0[s];
                sred[wc * 256 + rowL * 2 + 1] = d1[s];
            }
        }
        __syncthreads();
        if (tid < 128) {
            int grow = blockRow + tid;
            if (grow < M) {
                float D0 = sred[tid * 2 + 0] + sred[256 + tid * 2 + 0] + bp2[0];
                float D1 = sred[tid * 2 + 1] + sred[256 + tid * 2 + 1] + bp2[1];
                float mx = fmaxf(D0, D1);
                float e0 = expf(D0 - mx), e1 = expf(D1 - mx);
                probOut[grow] = e1 / (e0 + e1);
            }
        }
        return;
    }

    // ======== normal epilogue: bias + [relu] -> half C ========
#pragma unroll
    for (int mt = 0; mt < 2; mt++) {
#pragma unroll
        for (int nt = 0; nt < 8; nt++) {
            int col = wc * 64 + nt * 8 + lr * 2;
            float bias0 = bias[col], bias1 = bias[col + 1];
            int r0 = blockRow + wr * 32 + mt * 16 + lq;
            if (r0 < M) {
                float o0 = c[mt][nt][0] + bias0;
                float o1 = c[mt][nt][1] + bias1;
                if (doRelu) { o0 = fmaxf(o0, 0.f); o1 = fmaxf(o1, 0.f); }
                __half2 h = __floats2half2_rn(o0, o1);
                *(uint32_t*)(C + (size_t)r0 * D + col) = *(uint32_t*)&h;
            }
            int r1 = r0 + 8;
            if (r1 < M) {
                float o2 = c[mt][nt][2] + bias0;
                float o3 = c[mt][nt][3] + bias1;
                if (doRelu) { o2 = fmaxf(o2, 0.f); o3 = fmaxf(o3, 0.f); }
                __half2 h = __floats2half2_rn(o2, o3);
                *(uint32_t*)(C + (size_t)r1 * D + col) = *(uint32_t*)&h;
            }
        }
    }
}

// ---------------- predictor -------------------------------------------------
__global__ void buildz_k(const __half* __restrict__ h,
                         const int* __restrict__ ps, const int* __restrict__ pd,
                         const int* __restrict__ ns, const int* __restrict__ nd,
                         int P) {
    int t = blockIdx.x * blockDim.x + threadIdx.x;
    int row = t >> 4, l = t & 15;
    if (row >= 2 * P) return;
    int s, d;
    if (row < P) { s = ps[row]; d = pd[row]; }
    else         { s = ns[row - P]; d = nd[row - P]; }
    uint4 ua = *(const uint4*)(h + (size_t)s * D + l * 8);
    uint4 ub = *(const uint4*)(h + (size_t)d * D + l * 8);
    __half2 o0 = __hmul2(*(__half2*)&ua.x, *(__half2*)&ub.x);
    __half2 o1 = __hmul2(*(__half2*)&ua.y, *(__half2*)&ub.y);
    __half2 o2 = __hmul2(*(__half2*)&ua.z, *(__half2*)&ub.z);
    __half2 o3 = __hmul2(*(__half2*)&ua.w, *(__half2*)&ub.w);
    uint4 o;
    o.x = *(uint32_t*)&o0; o.y = *(uint32_t*)&o1;
    o.z = *(uint32_t*)&o2; o.w = *(uint32_t*)&o3;
    *(uint4*)(g_z + (size_t)row * D + l * 8) = o;
}

// ---------------- launch ----------------------------------------------------
extern "C" void kernel_launch(void* const* d_in, const int* in_sizes, int n_in,
                              void* d_out, int out_size) {
    const float* x   = (const float*)d_in[0];
    const int* src   = (const int*)d_in[1];
    const int* dst   = (const int*)d_in[2];
    const int* ps    = (const int*)d_in[3];
    const int* pd    = (const int*)d_in[4];
    const int* ns    = (const int*)d_in[5];
    const int* nd    = (const int*)d_in[6];
    const float* Ws0 = (const float*)d_in[7];
    const float* Wn0 = (const float*)d_in[8];
    const float* b0  = (const float*)d_in[9];
    const float* Ws1 = (const float*)d_in[10];
    const float* Wn1 = (const float*)d_in[11];
    const float* b1  = (const float*)d_in[12];
    const float* Ws2 = (const float*)d_in[13];
    const float* Wn2 = (const float*)d_in[14];
    const float* b2  = (const float*)d_in[15];
    const float* Wp0 = (const float*)d_in[16];
    const float* bp0 = (const float*)d_in[17];
    const float* Wp1 = (const float*)d_in[18];
    const float* bp1 = (const float*)d_in[19];
    const float* Wp2 = (const float*)d_in[20];
    const float* bp2 = (const float*)d_in[21];

    int N = in_sizes[0] / D;
    int E = in_sizes[1];
    int P = in_sizes[3];
    float* out = (float*)d_out;

    __half *hA, *hB, *hn, *z, *z2, *wcb;
    cudaGetSymbolAddress((void**)&hA, g_hA);
    cudaGetSymbolAddress((void**)&hB, g_hB);
    cudaGetSymbolAddress((void**)&hn, g_hn);
    cudaGetSymbolAddress((void**)&z,  g_z);
    cudaGetSymbolAddress((void**)&z2, g_z2);
    cudaGetSymbolAddress((void**)&wcb, g_wc);

    cudaFuncSetAttribute(gemm_tc_k, cudaFuncAttributeMaxDynamicSharedMemorySize, GEMM_SMEM);

    const __half* wc0 = wcb;
    const __half* wc1 = wcb + 1 * WELEM;
    const __half* wc2 = wcb + 2 * WELEM;
    const __half* wc3 = wcb + 3 * WELEM;
    const __half* wc4 = wcb + 4 * WELEM;
    const __half* wc5 = wcb + 5 * WELEM;
    const __half* wc6 = wcb + 6 * WELEM;
    const __half* wc7 = wcb + 7 * WELEM;

    WPtrs wp;
    wp.p[0] = Ws0; wp.p[1] = Wn0; wp.p[2] = Ws1; wp.p[3] = Wn1;
    wp.p[4] = Ws2; wp.p[5] = Wn2; wp.p[6] = Wp0; wp.p[7] = Wp1;

    int nb = (N + 511) / 512;
    int aggBlocks  = (N * 16 + 255) / 256;
    int gemmBlocksN = (N + 127) / 128;

    convw_k<<<dim3((WELEM + 255) / 256, 8), 256>>>(wp, wcb);
    convx_k<<<(N * D + 255) / 256, 256>>>(x, hB, N * D);
    zero_k<<<(N + 255) / 256, 256>>>(N);
    hist_k<<<(E + 255) / 256, 256>>>(dst, E);
    scan1_k<<<nb, 512>>>(N);
    scan2_k<<<1, 256>>>(nb);
    scan3_k<<<(N + 255) / 256, 256>>>(N);
    scatter_k<<<(E + 255) / 256, 256>>>(src, dst, E);

    // layer 0: hA = relu(xc@Ws0 + agg(xc)@Wn0 + b0)  [dual]
    agg_k<<<aggBlocks, 256>>>(hB, hn, N);
    gemm_tc_k<<<gemmBlocksN, 256, GEMM_SMEM>>>(hB, hn, wc0, wc1, b0, hA, N, 1,
                                               nullptr, nullptr, nullptr);
    // layer 1: hB = relu(hA@Ws1 + agg(hA)@Wn1 + b1)  [dual]
    agg_k<<<aggBlocks, 256>>>(hA, hn, N);
    gemm_tc_k<<<gemmBlocksN, 256, GEMM_SMEM>>>(hA, hn, wc2, wc3, b1, hB, N, 1,
                                               nullptr, nullptr, nullptr);
    // layer 2: hA = hB@Ws2 + agg(hB)@Wn2 + b2        [dual, no act]
    agg_k<<<aggBlocks, 256>>>(hB, hn, N);
    gemm_tc_k<<<gemmBlocksN, 256, GEMM_SMEM>>>(hB, hn, wc4, wc5, b2, hA, N, 0,
                                               nullptr, nullptr, nullptr);

    // predictor
    int M2 = 2 * P;
    int zBlocks16 = (M2 * 16 + 255) / 256;
    int gemmBlocksP = (M2 + 127) / 128;
    buildz_k<<<zBlocks16, 256>>>(hA, ps, pd, ns, nd, P);
    // G1: z2 = relu(z @ Wp0 + bp0)
    gemm_tc_k<<<gemmBlocksP, 256, GEMM_SMEM>>>(z, nullptr, wc6, nullptr, bp0, z2,
                                               M2, 1, nullptr, nullptr, nullptr);
    // G2 fused: out = softmax(relu(z2 @ Wp1 + bp1) @ Wp2 + bp2)[:,1]
    gemm_tc_k<<<gemmBlocksP, 256, GEMM_SMEM>>>(z2, nullptr, wc7, nullptr, bp1, nullptr,
                                               M2, 1, out, Wp2, bp2);
}

// round 17
// speedup vs baseline: 1.2116x; 1.0503x over previous
#include <cuda_runtime.h>
#include <cuda_fp16.h>
#include <math.h>
#include <stdint.h>

#define D 128
#define NMAX 100000
#define EMAX 800000
#define PMAX 100000
#define WELEM 16384

// ---------------- scratch (device globals; no allocation allowed) ----------
__device__ __align__(16) __half g_hA[NMAX * D];
__device__ __align__(16) __half g_hB[NMAX * D];   // holds half(x) for layer 0
__device__ __align__(16) __half g_hn[NMAX * D];
__device__ __align__(16) __half g_z[2 * PMAX * D];   // predictor z
__device__ __align__(16) __half g_wc[8 * WELEM];  // weights: half, transposed [n][k]
__device__ int   g_deg[NMAX];
__device__ int   g_rowstart[NMAX];
__device__ int   g_cursor[NMAX];
__device__ int   g_csrsrc[EMAX];
__device__ int   g_bsum[256];
__device__ int   g_boff[256];

// ---------------- operand pre-conversion -----------------------------------
struct WPtrs { const float* p[8]; };

__global__ void convw_k(WPtrs w, __half* out) {
    int m = blockIdx.y;
    int i = blockIdx.x * 256 + threadIdx.x;
    if (i < WELEM) {
        int k = i >> 7, n = i & 127;
        out[m * WELEM + n * 128 + k] = __float2half_rn(w.p[m][i]);
    }
}

__global__ void convx_k(const float* __restrict__ in, __half* __restrict__ out, int n) {
    int i = blockIdx.x * 256 + threadIdx.x;
    if (i < n) out[i] = __float2half_rn(in[i]);
}

// ---------------- CSR build ------------------------------------------------
__global__ void zero_k(int n) {
    int i = blockIdx.x * blockDim.x + threadIdx.x;
    if (i < n) { g_deg[i] = 0; g_cursor[i] = 0; }
}

__global__ void hist_k(const int* __restrict__ dst, int E) {
    int e = blockIdx.x * blockDim.x + threadIdx.x;
    if (e < E) atomicAdd(&g_deg[dst[e]], 1);
}

__global__ void scan1_k(int n) {
    __shared__ int s[512];
    int tid = threadIdx.x;
    int i = blockIdx.x * 512 + tid;
    int v = (i < n) ? g_deg[i] : 0;
    s[tid] = v;
    __syncthreads();
    for (int off = 1; off < 512; off <<= 1) {
        int t = (tid >= off) ? s[tid - off] : 0;
        __syncthreads();
        s[tid] += t;
        __syncthreads();
    }
    if (i < n) g_rowstart[i] = s[tid] - v;
    if (tid == 511) g_bsum[blockIdx.x] = s[511];
}

__global__ void scan2_k(int nb) {
    __shared__ int s[256];
    int tid = threadIdx.x;
    int v = (tid < nb) ? g_bsum[tid] : 0;
    s[tid] = v;
    __syncthreads();
    for (int off = 1; off < 256; off <<= 1) {
        int t = (tid >= off) ? s[tid - off] : 0;
        __syncthreads();
        s[tid] += t;
        __syncthreads();
    }
    g_boff[tid] = s[tid] - v;
}

__global__ void scan3_k(int n) {
    int i = blockIdx.x * blockDim.x + threadIdx.x;
    if (i < n) g_rowstart[i] += g_boff[i >> 9];
}

__global__ void scatter_k(const int* __restrict__ src, const int* __restrict__ dst, int E) {
    int e = blockIdx.x * blockDim.x + threadIdx.x;
    if (e >= E) return;
    int d = dst[e];
    int p = atomicAdd(&g_cursor[d], 1);
    g_csrsrc[g_rowstart[d] + p] = src[e];
}

// ---------------- mean aggregation: 16 lanes/node, uint4 loads -------------
__global__ void agg_k(const __half* __restrict__ h, __half* __restrict__ hn, int n) {
    int t = blockIdx.x * blockDim.x + threadIdx.x;
    int node = t >> 4, l = t & 15;
    if (node >= n) return;
    int st = g_rowstart[node], d = g_deg[node];
    float a0 = 0.f, a1 = 0.f, a2 = 0.f, a3 = 0.f;
    float a4 = 0.f, a5 = 0.f, a6 = 0.f, a7 = 0.f;
    for (int j = 0; j < d; j++) {
        int s = g_csrsrc[st + j];
        uint4 u = *(const uint4*)(h + (size_t)s * D + l * 8);
        float2 p0 = __half22float2(*(__half2*)&u.x);
        float2 p1 = __half22float2(*(__half2*)&u.y);
        float2 p2 = __half22float2(*(__half2*)&u.z);
        float2 p3 = __half22float2(*(__half2*)&u.w);
        a0 += p0.x; a1 += p0.y; a2 += p1.x; a3 += p1.y;
        a4 += p2.x; a5 += p2.y; a6 += p3.x; a7 += p3.y;
    }
    float inv = 1.f / fmaxf((float)d, 1.f);
    __half2 o0 = __floats2half2_rn(a0 * inv, a1 * inv);
    __half2 o1 = __floats2half2_rn(a2 * inv, a3 * inv);
    __half2 o2 = __floats2half2_rn(a4 * inv, a5 * inv);
    __half2 o3 = __floats2half2_rn(a6 * inv, a7 * inv);
    uint4 o;
    o.x = *(uint32_t*)&o0; o.y = *(uint32_t*)&o1;
    o.z = *(uint32_t*)&o2; o.w = *(uint32_t*)&o3;
    *(uint4*)(hn + (size_t)node * D + l * 8) = o;
}

// ---------------- shared GEMM pieces ---------------------------------------
#define BK 64
#define SAB_S 36
#define TILE_W (128 * SAB_S)
#define GEMM_SMEM (4 * TILE_W * 4)   // 73728

__device__ __forceinline__ void cp16(uint32_t dst, const void* src, bool pred) {
    int sz = pred ? 16 : 0;
    asm volatile("cp.async.cg.shared.global [%0], [%1], 16, %2;\n"
                 :: "r"(dst), "l"(src), "r"(sz));
}

__device__ __forceinline__ void ldsm4(uint32_t& r0, uint32_t& r1, uint32_t& r2,
                                      uint32_t& r3, uint32_t addr) {
    asm volatile("ldmatrix.sync.aligned.m8n8.x4.shared.b16 {%0,%1,%2,%3}, [%4];"
                 : "=r"(r0), "=r"(r1), "=r"(r2), "=r"(r3) : "r"(addr));
}

#define MMA16816(cc, aa, bb)                                                  \
    asm volatile(                                                             \
        "mma.sync.aligned.m16n8k16.row.col.f32.f16.f16.f32 "                  \
        "{%0,%1,%2,%3}, {%4,%5,%6,%7}, {%8,%9}, {%0,%1,%2,%3};"               \
        : "+f"((cc)[0]), "+f"((cc)[1]), "+f"((cc)[2]), "+f"((cc)[3])          \
        : "r"((aa)[0]), "r"((aa)[1]), "r"((aa)[2]), "r"((aa)[3]),             \
          "r"((bb)[0]), "r"((bb)[1]))

// ---------------- layer GEMM (round-16 core) --------------------------------
// 128x128 tile, 8 warps 4x2, BK=64, cp.async 2-buffer, ldmatrix. Dual via A2/W2.
__global__ void __launch_bounds__(256) gemm_tc_k(
    const __half* __restrict__ A, const __half* __restrict__ A2,
    const __half* __restrict__ W, const __half* __restrict__ W2,
    const float* __restrict__ bias, __half* __restrict__ C,
    int M, int doRelu)
{
    extern __shared__ uint32_t smem[];
    int tid = threadIdx.x;
    int lane = tid & 31;
    int w = tid >> 5;
    int wr = w >> 1, wc = w & 1;
    int blockRow = blockIdx.x * 128;
    int lq = lane >> 2;
    int lr = lane & 3;

    uint32_t sbase = (uint32_t)__cvta_generic_to_shared(smem);

    int T = (A2 != nullptr) ? 4 : 2;

    int aRowOff0 = (wr * 32 + (lane & 7) + ((lane >> 3) & 1) * 8) * SAB_S
                 + (lane >> 4) * 4;
    int bRowOff0 = (wc * 64 + ((lane >> 4) & 1) * 8 + (lane & 7)) * SAB_S
                 + ((lane >> 3) & 1) * 4;

    float c[2][8][4];
#pragma unroll
    for (int mt = 0; mt < 2; mt++)
#pragma unroll
        for (int nt = 0; nt < 8; nt++)
#pragma unroll
            for (int i = 0; i < 4; i++) c[mt][nt][i] = 0.f;

    auto loadTile = [&](int t, int buf) {
        const __half* Ap = (t >> 1) ? A2 : A;
        const __half* Wp = (t >> 1) ? W2 : W;
        int kt = (t & 1) * BK;
        uint32_t dA = sbase + (uint32_t)buf * 2 * TILE_W * 4;
        uint32_t dB = dA + TILE_W * 4;
#pragma unroll
        for (int i = 0; i < 4; i++) {
            int q = tid + i * 256;
            int r = q >> 3, ch = q & 7;
            int grow = blockRow + r;
            cp16(dA + (uint32_t)(r * SAB_S + ch * 4) * 4,
                 Ap + (size_t)grow * D + kt + ch * 8, grow < M);
        }
#pragma unroll
        for (int i = 0; i < 4; i++) {
            int q = tid + i * 256;
            int r = q >> 3, ch = q & 7;
            cp16(dB + (uint32_t)(r * SAB_S + ch * 4) * 4,
                 Wp + (size_t)r * D + kt + ch * 8, true);
        }
    };

    loadTile(0, 0);
    asm volatile("cp.async.commit_group;\n");

#pragma unroll 1
    for (int t = 0; t < 4; t++) {
        if (t >= T) break;
        int buf = t & 1;
        if (t + 1 < T) loadTile(t + 1, buf ^ 1);
        asm volatile("cp.async.commit_group;\n");
        asm volatile("cp.async.wait_group 1;\n");
        __syncthreads();

        uint32_t tAaddr = sbase + (uint32_t)(buf * 2 * TILE_W) * 4;
        uint32_t tBaddr = tAaddr + TILE_W * 4;
#pragma unroll
        for (int ks = 0; ks < 4; ks++) {
            int kw = ks * 8;
            uint32_t a[2][4];
#pragma unroll
            for (int mt = 0; mt < 2; mt++)
                ldsm4(a[mt][0], a[mt][1], a[mt][2], a[mt][3],
                      tAaddr + (uint32_t)(aRowOff0 + mt * 16 * SAB_S + kw) * 4);
            uint32_t b[8][2];
#pragma unroll
            for (int j = 0; j < 4; j++)
                ldsm4(b[2 * j][0], b[2 * j][1], b[2 * j + 1][0], b[2 * j + 1][1],
                      tBaddr + (uint32_t)(bRowOff0 + j * 16 * SAB_S + kw) * 4);
#pragma unroll
            for (int mt = 0; mt < 2; mt++)
#pragma unroll
                for (int nt = 0; nt < 8; nt++)
                    MMA16816(c[mt][nt], a[mt], b[nt]);
        }
        __syncthreads();
    }

    // epilogue: bias + [relu] -> half C
#pragma unroll
    for (int mt = 0; mt < 2; mt++) {
#pragma unroll
        for (int nt = 0; nt < 8; nt++) {
            int col = wc * 64 + nt * 8 + lr * 2;
            float bias0 = bias[col], bias1 = bias[col + 1];
            int r0 = blockRow + wr * 32 + mt * 16 + lq;
            if (r0 < M) {
                float o0 = c[mt][nt][0] + bias0;
                float o1 = c[mt][nt][1] + bias1;
                if (doRelu) { o0 = fmaxf(o0, 0.f); o1 = fmaxf(o1, 0.f); }
                __half2 h = __floats2half2_rn(o0, o1);
                *(uint32_t*)(C + (size_t)r0 * D + col) = *(uint32_t*)&h;
            }
            int r1 = r0 + 8;
            if (r1 < M) {
                float o2 = c[mt][nt][2] + bias0;
                float o3 = c[mt][nt][3] + bias1;
                if (doRelu) { o2 = fmaxf(o2, 0.f); o3 = fmaxf(o3, 0.f); }
                __half2 h = __floats2half2_rn(o2, o3);
                *(uint32_t*)(C + (size_t)r1 * D + col) = *(uint32_t*)&h;
            }
        }
    }
}

// ---------------- chained predictor GEMM ------------------------------------
// out = softmax( relu( relu(z@Wp0+bp0) @ Wp1 + bp1 ) @ Wp2 + bp2 )[:,1]
// Stage 1: standard mainloop, A=z (cp.async), W=Wp0; result -> smem (half,
// A-tile layout, both K-slabs at word offsets 0 / TILE_W).
// Stage 2: A resident in smem, B=Wp1 (cp.async into 2*TILE_W / 3*TILE_W);
// probOut epilogue with bias=bp1.
__global__ void __launch_bounds__(256) gemm_pred_k(
    const __half* __restrict__ Z,
    const __half* __restrict__ W0, const float* __restrict__ bp0,
    const __half* __restrict__ W1, const float* __restrict__ bp1,
    const float* __restrict__ Wp2, const float* __restrict__ bp2,
    float* __restrict__ probOut, int M)
{
    extern __shared__ uint32_t smem[];
    int tid = threadIdx.x;
    int lane = tid & 31;
    int w = tid >> 5;
    int wr = w >> 1, wc = w & 1;
    int blockRow = blockIdx.x * 128;
    int lq = lane >> 2;
    int lr = lane & 3;

    uint32_t sbase = (uint32_t)__cvta_generic_to_shared(smem);

    int aRowOff0 = (wr * 32 + (lane & 7) + ((lane >> 3) & 1) * 8) * SAB_S
                 + (lane >> 4) * 4;
    int bRowOff0 = (wc * 64 + ((lane >> 4) & 1) * 8 + (lane & 7)) * SAB_S
                 + ((lane >> 3) & 1) * 4;

    float c[2][8][4];
#pragma unroll
    for (int mt = 0; mt < 2; mt++)
#pragma unroll
        for (int nt = 0; nt < 8; nt++)
#pragma unroll
            for (int i = 0; i < 4; i++) c[mt][nt][i] = 0.f;

    // ---- stage 1: z @ W0 ----
    auto loadTile1 = [&](int t, int buf) {
        int kt = t * BK;
        uint32_t dA = sbase + (uint32_t)buf * 2 * TILE_W * 4;
        uint32_t dB = dA + TILE_W * 4;
#pragma unroll
        for (int i = 0; i < 4; i++) {
            int q = tid + i * 256;
            int r = q >> 3, ch = q & 7;
            int grow = blockRow + r;
            cp16(dA + (uint32_t)(r * SAB_S + ch * 4) * 4,
                 Z + (size_t)grow * D + kt + ch * 8, grow < M);
        }
#pragma unroll
        for (int i = 0; i < 4; i++) {
            int q = tid + i * 256;
            int r = q >> 3, ch = q & 7;
            cp16(dB + (uint32_t)(r * SAB_S + ch * 4) * 4,
                 W0 + (size_t)r * D + kt + ch * 8, true);
        }
    };

    loadTile1(0, 0);
    asm volatile("cp.async.commit_group;\n");

#pragma unroll 1
    for (int t = 0; t < 2; t++) {
        int buf = t & 1;
        if (t + 1 < 2) loadTile1(t + 1, buf ^ 1);
        asm volatile("cp.async.commit_group;\n");
        asm volatile("cp.async.wait_group 1;\n");
        __syncthreads();

        uint32_t tAaddr = sbase + (uint32_t)(buf * 2 * TILE_W) * 4;
        uint32_t tBaddr = tAaddr + TILE_W * 4;
#pragma unroll
        for (int ks = 0; ks < 4; ks++) {
            int kw = ks * 8;
            uint32_t a[2][4];
#pragma unroll
            for (int mt = 0; mt < 2; mt++)
                ldsm4(a[mt][0], a[mt][1], a[mt][2], a[mt][3],
                      tAaddr + (uint32_t)(aRowOff0 + mt * 16 * SAB_S + kw) * 4);
            uint32_t b[8][2];
#pragma unroll
            for (int j = 0; j < 4; j++)
                ldsm4(b[2 * j][0], b[2 * j][1], b[2 * j + 1][0], b[2 * j + 1][1],
                      tBaddr + (uint32_t)(bRowOff0 + j * 16 * SAB_S + kw) * 4);
#pragma unroll
            for (int mt = 0; mt < 2; mt++)
#pragma unroll
                for (int nt = 0; nt < 8; nt++)
                    MMA16816(c[mt][nt], a[mt], b[nt]);
        }
        __syncthreads();
    }

    // ---- stage-1 epilogue: relu(c + bp0) -> half -> smem A-tile layout ----
    // col = wc*64 + nt*8 + lr*2 ; slab = wc ; word = wc*TILE_W + r*36 + nt*4 + lr
#pragma unroll
    for (int mt = 0; mt < 2; mt++) {
#pragma unroll
        for (int nt = 0; nt < 8; nt++) {
            int col = wc * 64 + nt * 8 + lr * 2;
            float bias0 = bp0[col], bias1 = bp0[col + 1];
            int wordCol = nt * 4 + lr;
            int r0 = wr * 32 + mt * 16 + lq;
            {
                float o0 = fmaxf(c[mt][nt][0] + bias0, 0.f);
                float o1 = fmaxf(c[mt][nt][1] + bias1, 0.f);
                __half2 h = __floats2half2_rn(o0, o1);
                smem[wc * TILE_W + r0 * SAB_S + wordCol] = *(uint32_t*)&h;
            }
            {
                float o2 = fmaxf(c[mt][nt][2] + bias0, 0.f);
                float o3 = fmaxf(c[mt][nt][3] + bias1, 0.f);
                __half2 h = __floats2half2_rn(o2, o3);
                smem[wc * TILE_W + (r0 + 8) * SAB_S + wordCol] = *(uint32_t*)&h;
            }
        }
    }

    // reset accumulators; load both Wp1 slabs into regions 2,3
#pragma unroll
    for (int mt = 0; mt < 2; mt++)
#pragma unroll
        for (int nt = 0; nt < 8; nt++)
#pragma unroll
            for (int i = 0; i < 4; i++) c[mt][nt][i] = 0.f;

#pragma unroll
    for (int t = 0; t < 2; t++) {
        uint32_t dB = sbase + (uint32_t)(2 + t) * TILE_W * 4;
        int kt = t * BK;
#pragma unroll
        for (int i = 0; i < 4; i++) {
            int q = tid + i * 256;
            int r = q >> 3, ch = q & 7;
            cp16(dB + (uint32_t)(r * SAB_S + ch * 4) * 4,
                 W1 + (size_t)r * D + kt + ch * 8, true);
        }
    }
    asm volatile("cp.async.commit_group;\n");
    asm volatile("cp.async.wait_group 0;\n");
    __syncthreads();   // A-tile stores + B cp.async visible to all

    // ---- stage 2: z2(smem) @ W1 ----
#pragma unroll 1
    for (int t = 0; t < 2; t++) {
        uint32_t tAaddr = sbase + (uint32_t)(t * TILE_W) * 4;
        uint32_t tBaddr = sbase + (uint32_t)((2 + t) * TILE_W) * 4;
#pragma unroll
        for (int ks = 0; ks < 4; ks++) {
            int kw = ks * 8;
            uint32_t a[2][4];
#pragma unroll
            for (int mt = 0; mt < 2; mt++)
                ldsm4(a[mt][0], a[mt][1], a[mt][2], a[mt][3],
                      tAaddr + (uint32_t)(aRowOff0 + mt * 16 * SAB_S + kw) * 4);
            uint32_t b[8][2];
#pragma unroll
            for (int j = 0; j < 4; j++)
                ldsm4(b[2 * j][0], b[2 * j][1], b[2 * j + 1][0], b[2 * j + 1][1],
                      tBaddr + (uint32_t)(bRowOff0 + j * 16 * SAB_S + kw) * 4);
#pragma unroll
            for (int mt = 0; mt < 2; mt++)
#pragma unroll
                for (int nt = 0; nt < 8; nt++)
                    MMA16816(c[mt][nt], a[mt], b[nt]);
        }
    }
    __syncthreads();   // stage-2 reads done before sred reuses smem

    // ---- probOut epilogue: bias(bp1)+relu+Wp2 dot+softmax ----
    {
        float d0[4] = {0.f, 0.f, 0.f, 0.f};
        float d1[4] = {0.f, 0.f, 0.f, 0.f};
#pragma unroll
        for (int mt = 0; mt < 2; mt++) {
#pragma unroll
            for (int nt = 0; nt < 8; nt++) {
                int col = wc * 64 + nt * 8 + lr * 2;
                float bias0 = bp1[col], bias1 = bp1[col + 1];
                float w20 = Wp2[col * 2 + 0],       w21 = Wp2[col * 2 + 1];
                float w30 = Wp2[(col + 1) * 2 + 0], w31 = Wp2[(col + 1) * 2 + 1];
                float v0 = fmaxf(c[mt][nt][0] + bias0, 0.f);
                float v1 = fmaxf(c[mt][nt][1] + bias1, 0.f);
                float v2 = fmaxf(c[mt][nt][2] + bias0, 0.f);
                float v3 = fmaxf(c[mt][nt][3] + bias1, 0.f);
                d0[mt * 2 + 0] += v0 * w20 + v1 * w30;
                d1[mt * 2 + 0] += v0 * w21 + v1 * w31;
                d0[mt * 2 + 1] += v2 * w20 + v3 * w30;
                d1[mt * 2 + 1] += v2 * w21 + v3 * w31;
            }
        }
#pragma unroll
        for (int s = 0; s < 4; s++) {
            d0[s] += __shfl_xor_sync(0xffffffffu, d0[s], 1);
            d0[s] += __shfl_xor_sync(0xffffffffu, d0[s], 2);
            d1[s] += __shfl_xor_sync(0xffffffffu, d1[s], 1);
            d1[s] += __shfl_xor_sync(0xffffffffu, d1[s], 2);
        }
        float* sred = (float*)smem;
        if (lr == 0) {
#pragma unroll
            for (int s = 0; s < 4; s++) {
                int mt = s >> 1, half = s & 1;
                int rowL = wr * 32 + mt * 16 + half * 8 + lq;
                sred[wc * 256 + rowL * 2 + 0] = d0[s];
                sred[wc * 256 + rowL * 2 + 1] = d1[s];
            }
        }
        __syncthreads();
        if (tid < 128) {
            int grow = blockRow + tid;
            if (grow < M) {
                float D0 = sred[tid * 2 + 0] + sred[256 + tid * 2 + 0] + bp2[0];
                float D1 = sred[tid * 2 + 1] + sred[256 + tid * 2 + 1] + bp2[1];
                float mx = fmaxf(D0, D1);
                float e0 = expf(D0 - mx), e1 = expf(D1 - mx);
                probOut[grow] = e1 / (e0 + e1);
            }
        }
    }
}

// ---------------- predictor z build -----------------------------------------
__global__ void buildz_k(const __half* __restrict__ h,
                         const int* __restrict__ ps, const int* __restrict__ pd,
                         const int* __restrict__ ns, const int* __restrict__ nd,
                         int P) {
    int t = blockIdx.x * blockDim.x + threadIdx.x;
    int row = t >> 4, l = t & 15;
    if (row >= 2 * P) return;
    int s, d;
    if (row < P) { s = ps[row]; d = pd[row]; }
    else         { s = ns[row - P]; d = nd[row - P]; }
    uint4 ua = *(const uint4*)(h + (size_t)s * D + l * 8);
    uint4 ub = *(const uint4*)(h + (size_t)d * D + l * 8);
    __half2 o0 = __hmul2(*(__half2*)&ua.x, *(__half2*)&ub.x);
    __half2 o1 = __hmul2(*(__half2*)&ua.y, *(__half2*)&ub.y);
    __half2 o2 = __hmul2(*(__half2*)&ua.z, *(__half2*)&ub.z);
    __half2 o3 = __hmul2(*(__half2*)&ua.w, *(__half2*)&ub.w);
    uint4 o;
    o.x = *(uint32_t*)&o0; o.y = *(uint32_t*)&o1;
    o.z = *(uint32_t*)&o2; o.w = *(uint32_t*)&o3;
    *(uint4*)(g_z + (size_t)row * D + l * 8) = o;
}

// ---------------- launch ----------------------------------------------------
extern "C" void kernel_launch(void* const* d_in, const int* in_sizes, int n_in,
                              void* d_out, int out_size) {
    const float* x   = (const float*)d_in[0];
    const int* src   = (const int*)d_in[1];
    const int* dst   = (const int*)d_in[2];
    const int* ps    = (const int*)d_in[3];
    const int* pd    = (const int*)d_in[4];
    const int* ns    = (const int*)d_in[5];
    const int* nd    = (const int*)d_in[6];
    const float* Ws0 = (const float*)d_in[7];
    const float* Wn0 = (const float*)d_in[8];
    const float* b0  = (const float*)d_in[9];
    const float* Ws1 = (const float*)d_in[10];
    const float* Wn1 = (const float*)d_in[11];
    const float* b1  = (const float*)d_in[12];
    const float* Ws2 = (const float*)d_in[13];
    const float* Wn2 = (const float*)d_in[14];
    const float* b2  = (const float*)d_in[15];
    const float* Wp0 = (const float*)d_in[16];
    const float* bp0 = (const float*)d_in[17];
    const float* Wp1 = (const float*)d_in[18];
    const float* bp1 = (const float*)d_in[19];
    const float* Wp2 = (const float*)d_in[20];
    const float* bp2 = (const float*)d_in[21];

    int N = in_sizes[0] / D;
    int E = in_sizes[1];
    int P = in_sizes[3];
    float* out = (float*)d_out;

    __half *hA, *hB, *hn, *z, *wcb;
    cudaGetSymbolAddress((void**)&hA, g_hA);
    cudaGetSymbolAddress((void**)&hB, g_hB);
    cudaGetSymbolAddress((void**)&hn, g_hn);
    cudaGetSymbolAddress((void**)&z,  g_z);
    cudaGetSymbolAddress((void**)&wcb, g_wc);

    cudaFuncSetAttribute(gemm_tc_k,   cudaFuncAttributeMaxDynamicSharedMemorySize, GEMM_SMEM);
    cudaFuncSetAttribute(gemm_pred_k, cudaFuncAttributeMaxDynamicSharedMemorySize, GEMM_SMEM);

    const __half* wc0 = wcb;
    const __half* wc1 = wcb + 1 * WELEM;
    const __half* wc2 = wcb + 2 * WELEM;
    const __half* wc3 = wcb + 3 * WELEM;
    const __half* wc4 = wcb + 4 * WELEM;
    const __half* wc5 = wcb + 5 * WELEM;
    const __half* wc6 = wcb + 6 * WELEM;
    const __half* wc7 = wcb + 7 * WELEM;

    WPtrs wp;
    wp.p[0] = Ws0; wp.p[1] = Wn0; wp.p[2] = Ws1; wp.p[3] = Wn1;
    wp.p[4] = Ws2; wp.p[5] = Wn2; wp.p[6] = Wp0; wp.p[7] = Wp1;

    int nb = (N + 511) / 512;
    int aggBlocks  = (N * 16 + 255) / 256;
    int gemmBlocksN = (N + 127) / 128;

    convw_k<<<dim3((WELEM + 255) / 256, 8), 256>>>(wp, wcb);
    convx_k<<<(N * D + 255) / 256, 256>>>(x, hB, N * D);
    zero_k<<<(N + 255) / 256, 256>>>(N);
    hist_k<<<(E + 255) / 256, 256>>>(dst, E);
    scan1_k<<<nb, 512>>>(N);
    scan2_k<<<1, 256>>>(nb);
    scan3_k<<<(N + 255) / 256, 256>>>(N);
    scatter_k<<<(E + 255) / 256, 256>>>(src, dst, E);

    // layer 0: hA = relu(xc@Ws0 + agg(xc)@Wn0 + b0)  [dual]
    agg_k<<<aggBlocks, 256>>>(hB, hn, N);
    gemm_tc_k<<<gemmBlocksN, 256, GEMM_SMEM>>>(hB, hn, wc0, wc1, b0, hA, N, 1);
    // layer 1: hB = relu(hA@Ws1 + agg(hA)@Wn1 + b1)  [dual]
    agg_k<<<aggBlocks, 256>>>(hA, hn, N);
    gemm_tc_k<<<gemmBlocksN, 256, GEMM_SMEM>>>(hA, hn, wc2, wc3, b1, hB, N, 1);
    // layer 2: hA = hB@Ws2 + agg(hB)@Wn2 + b2        [dual, no act]
    agg_k<<<aggBlocks, 256>>>(hB, hn, N);
    gemm_tc_k<<<gemmBlocksN, 256, GEMM_SMEM>>>(hB, hn, wc4, wc5, b2, hA, N, 0);

    // predictor: buildz then one chained GEMM (G1+G2+softmax fused)
    int M2 = 2 * P;
    int zBlocks16 = (M2 * 16 + 255) / 256;
    int gemmBlocksP = (M2 + 127) / 128;
    buildz_k<<<zBlocks16, 256>>>(hA, ps, pd, ns, nd, P);
    gemm_pred_k<<<gemmBlocksP, 256, GEMM_SMEM>>>(z, wc6, bp0, wc7, bp1,
                                                 Wp2, bp2, out, M2);
}